// round 1
// baseline (speedup 1.0000x reference)
#include <cuda_runtime.h>

// ---------------------------------------------------------------------------
// MultiHeadAreaAttention, restructured:
//   qh/kh/vh = proj(q/k/v)                      [BH=128, L=512, 64]
//   S[bh,t,j] = qh_t . kh_j   (j <= t needed)   [128, 512, 512]
//   per row t:  C = cumsum_j(S),  logits(w,e) = (C_e - C_{e-w})/w, e<=t
//               softmax over all (w,e) visible; fold back:
//               G_j = P1[j] + P2[j]+P2[j+1] + P3[j]+P3[j+1]+P3[j+2]   (in-place over S)
//   attn = G @ vh  -> [B, L, H*DV] layout
//   out  = attn @ Wo + bo
// ---------------------------------------------------------------------------

#define BH_ 128
#define L_  512
#define DH_ 64

__device__ float g_Qh[BH_ * L_ * DH_];
__device__ float g_Kh[BH_ * L_ * DH_];
__device__ float g_Vh[BH_ * L_ * DH_];
__device__ float g_S[(size_t)BH_ * L_ * L_];      // scores, then G in-place
__device__ float g_attn[16 * L_ * 512];           // [B, L, H*DV]

// ---------------------------------------------------------------------------
// Dense SGEMM: Y[8192,512] = X[8192,512] @ W[512,512] + bias
// MODE 0/1/2: head-split epilogue into g_Qh/g_Kh/g_Vh
// MODE 3:     plain row-major into Y (final output), X taken from g_attn
// ---------------------------------------------------------------------------
template <int MODE>
__global__ __launch_bounds__(256) void sgemm_kernel(
    const float* __restrict__ X, const float* __restrict__ Wm,
    const float* __restrict__ bias, float* __restrict__ Y)
{
    constexpr int BK = 8;
    __shared__ float As[BK][128];
    __shared__ float Bs[BK][128];

    const float* Xp = (MODE == 3) ? (const float*)g_attn : X;
    float* outp = (MODE == 0) ? g_Qh : (MODE == 1) ? g_Kh : (MODE == 2) ? g_Vh : Y;

    int tid  = threadIdx.x;
    int row0 = blockIdx.y * 128;
    int col0 = blockIdx.x * 128;
    int arow = tid >> 1, acol = (tid & 1) * 4;
    int brow = tid >> 5, bcol = (tid & 31) * 4;
    int tx = tid & 15, ty = tid >> 4;

    float acc[8][8];
#pragma unroll
    for (int i = 0; i < 8; i++)
#pragma unroll
        for (int j = 0; j < 8; j++) acc[i][j] = 0.f;

    for (int k0 = 0; k0 < 512; k0 += BK) {
        float4 av = *(const float4*)(Xp + (size_t)(row0 + arow) * 512 + k0 + acol);
        As[acol + 0][arow] = av.x;
        As[acol + 1][arow] = av.y;
        As[acol + 2][arow] = av.z;
        As[acol + 3][arow] = av.w;
        *(float4*)&Bs[brow][bcol] =
            *(const float4*)(Wm + (size_t)(k0 + brow) * 512 + col0 + bcol);
        __syncthreads();
#pragma unroll
        for (int k = 0; k < BK; k++) {
            float a[8], b[8];
            *(float4*)(a)     = *(float4*)&As[k][ty * 8];
            *(float4*)(a + 4) = *(float4*)&As[k][ty * 8 + 4];
            *(float4*)(b)     = *(float4*)&Bs[k][tx * 8];
            *(float4*)(b + 4) = *(float4*)&Bs[k][tx * 8 + 4];
#pragma unroll
            for (int i = 0; i < 8; i++)
#pragma unroll
                for (int j = 0; j < 8; j++) acc[i][j] += a[i] * b[j];
        }
        __syncthreads();
    }

#pragma unroll
    for (int i = 0; i < 8; i++) {
        int r = row0 + ty * 8 + i;
#pragma unroll
        for (int j = 0; j < 8; j++) {
            int c = col0 + tx * 8 + j;
            float v = acc[i][j] + bias[c];
            if (MODE == 3) {
                outp[(size_t)r * 512 + c] = v;
            } else {
                int b_ = r >> 9, l = r & 511;
                int h  = c >> 6, d = c & 63;
                outp[(((size_t)(b_ * 8 + h) * 512 + l) << 6) + d] = v;
            }
        }
    }
}

// ---------------------------------------------------------------------------
// Batched S = Qh @ Kh^T  per bh.  64x64 tiles, K=64.  Skip upper triangle.
// ---------------------------------------------------------------------------
__global__ __launch_bounds__(256) void qk_kernel()
{
    int tk = blockIdx.x, tq = blockIdx.y, bh = blockIdx.z;
    if (tk > tq) return;

    __shared__ float Qs[64][68];
    __shared__ float Ks[64][68];
    const float* Q = g_Qh + (size_t)bh * L_ * DH_;
    const float* K = g_Kh + (size_t)bh * L_ * DH_;
    int tid = threadIdx.x;

#pragma unroll
    for (int i = 0; i < 4; i++) {
        int e = tid + i * 256;
        int r = e >> 4, c4 = (e & 15) * 4;
        *(float4*)&Qs[r][c4] = *(const float4*)(Q + (size_t)(tq * 64 + r) * 64 + c4);
        *(float4*)&Ks[r][c4] = *(const float4*)(K + (size_t)(tk * 64 + r) * 64 + c4);
    }
    __syncthreads();

    int tx = tid & 15, ty = tid >> 4;
    float acc[4][4] = {};
#pragma unroll 8
    for (int k = 0; k < 64; k++) {
        float a[4], b[4];
#pragma unroll
        for (int i = 0; i < 4; i++) a[i] = Qs[ty * 4 + i][k];
#pragma unroll
        for (int j = 0; j < 4; j++) b[j] = Ks[tx * 4 + j][k];
#pragma unroll
        for (int i = 0; i < 4; i++)
#pragma unroll
            for (int j = 0; j < 4; j++) acc[i][j] += a[i] * b[j];
    }

    float* Smat = g_S + (size_t)bh * L_ * L_;
#pragma unroll
    for (int i = 0; i < 4; i++)
#pragma unroll
        for (int j = 0; j < 4; j++)
            Smat[(size_t)(tq * 64 + ty * 4 + i) * 512 + tk * 64 + tx * 4 + j] = acc[i][j];
}

// ---------------------------------------------------------------------------
// Per-row: cumsum, area logits for w=1..3, masked softmax, fold to G (in-place)
// One warp per query row t. 4 warps / CTA.
// ---------------------------------------------------------------------------
__global__ __launch_bounds__(128) void area_softmax_kernel()
{
    __shared__ float Cb[4][516];  // Cb[w][0]=0 ; Cb[w][1+e] = inclusive cumsum
    __shared__ float Tb[4][516];  // p1+p2+p3 at end e
    __shared__ float Ub[4][516];  // p2+p3
    __shared__ float Vb[4][516];  // p3

    int wrp  = threadIdx.x >> 5;
    int lane = threadIdx.x & 31;
    int t    = blockIdx.x * 4 + wrp;
    int bh   = blockIdx.y;

    float* Srow = g_S + ((size_t)bh * L_ + t) * L_;
    float* C = Cb[wrp];
    float* T = Tb[wrp];
    float* U = Ub[wrp];
    float* V = Vb[wrp];

    // inclusive cumsum of s_j for j=0..t into C[1+j], C[0]=0
    if (lane == 0) C[0] = 0.f;
    float carry = 0.f;
    int nchunk = (t + 32) >> 5;
    for (int c0 = 0; c0 < nchunk; c0++) {
        int j = c0 * 32 + lane;
        float s = (j <= t) ? Srow[j] : 0.f;
#pragma unroll
        for (int off = 1; off < 32; off <<= 1) {
            float y = __shfl_up_sync(0xffffffffu, s, off);
            if (lane >= off) s += y;
        }
        s += carry;
        C[1 + j] = s;
        carry = __shfl_sync(0xffffffffu, s, 31);
    }
    __syncwarp();

    // running max over all visible area logits
    float m = -1e30f;
    for (int e = lane; e <= t; e += 32) {
        float ce = C[1 + e];
        m = fmaxf(m, ce - C[e]);                                  // w=1
        if (e >= 1) m = fmaxf(m, (ce - C[e - 1]) * 0.5f);         // w=2
        if (e >= 2) m = fmaxf(m, (ce - C[e - 2]) * (1.f / 3.f));  // w=3
    }
#pragma unroll
    for (int off = 16; off; off >>= 1) m = fmaxf(m, __shfl_xor_sync(0xffffffffu, m, off));

    // exp, partial fold, denominator
    float sum = 0.f;
    for (int e = lane; e < 512; e += 32) {
        float p1 = 0.f, p2 = 0.f, p3 = 0.f;
        if (e <= t) {
            float ce = C[1 + e];
            p1 = __expf(ce - C[e] - m);
            if (e >= 1) p2 = __expf((ce - C[e - 1]) * 0.5f - m);
            if (e >= 2) p3 = __expf((ce - C[e - 2]) * (1.f / 3.f) - m);
        }
        T[e] = p1 + p2 + p3;
        U[e] = p2 + p3;
        V[e] = p3;
        sum += p1 + p2 + p3;
    }
    if (lane < 2) { T[512 + lane] = 0.f; U[512 + lane] = 0.f; V[512 + lane] = 0.f; }
#pragma unroll
    for (int off = 16; off; off >>= 1) sum += __shfl_xor_sync(0xffffffffu, sum, off);
    float inv = 1.f / sum;
    __syncwarp();

    // G_j = T[j] + U[j+1] + V[j+2], normalized; zero beyond t. In-place over S.
    for (int j = lane; j < 512; j += 32) {
        float g = (j <= t) ? (T[j] + U[j + 1] + V[j + 2]) * inv : 0.f;
        Srow[j] = g;
    }
}

// ---------------------------------------------------------------------------
// Batched attn = G @ Vh per bh.  M=512, N=64, K=512 (triangular K-loop).
// Epilogue writes [B, L, H*DV] layout.
// ---------------------------------------------------------------------------
__global__ __launch_bounds__(256) void av_kernel()
{
    int tm = blockIdx.x, bh = blockIdx.y;
    __shared__ float Gs[64][36];
    __shared__ float Vs[32][68];
    const float* G  = g_S + (size_t)bh * L_ * L_;
    const float* Vh = g_Vh + (size_t)bh * L_ * DH_;
    int tid = threadIdx.x, tx = tid & 15, ty = tid >> 4;

    float acc[4][4] = {};
    int nkt = (tm + 1) * 2;  // only j <= tm*64+63 can be nonzero
    for (int kt = 0; kt < nkt; kt++) {
#pragma unroll
        for (int i = 0; i < 2; i++) {
            int e = tid + i * 256;
            int r = e >> 3, c4 = (e & 7) * 4;
            *(float4*)&Gs[r][c4] =
                *(const float4*)(G + (size_t)(tm * 64 + r) * 512 + kt * 32 + c4);
        }
#pragma unroll
        for (int i = 0; i < 2; i++) {
            int e = tid + i * 256;
            int r = e >> 4, c4 = (e & 15) * 4;
            *(float4*)&Vs[r][c4] = *(const float4*)(Vh + (size_t)(kt * 32 + r) * 64 + c4);
        }
        __syncthreads();
#pragma unroll 8
        for (int k = 0; k < 32; k++) {
            float a[4], b[4];
#pragma unroll
            for (int i = 0; i < 4; i++) a[i] = Gs[ty * 4 + i][k];
#pragma unroll
            for (int j = 0; j < 4; j++) b[j] = Vs[k][tx * 4 + j];
#pragma unroll
            for (int i = 0; i < 4; i++)
#pragma unroll
                for (int j = 0; j < 4; j++) acc[i][j] += a[i] * b[j];
        }
        __syncthreads();
    }

    int b = bh >> 3, h = bh & 7;
#pragma unroll
    for (int i = 0; i < 4; i++) {
        int t = tm * 64 + ty * 4 + i;
#pragma unroll
        for (int j = 0; j < 4; j++) {
            int d = tx * 4 + j;
            g_attn[(size_t)(b * 512 + t) * 512 + h * 64 + d] = acc[i][j];
        }
    }
}

// ---------------------------------------------------------------------------
extern "C" void kernel_launch(void* const* d_in, const int* in_sizes, int n_in,
                              void* d_out, int out_size)
{
    const float* q  = (const float*)d_in[0];
    const float* k  = (const float*)d_in[1];
    const float* v  = (const float*)d_in[2];
    // d_in[3] = attn_mask (bool) — mask is analytic (area end <= t), unused.
    const float* Wq = (const float*)d_in[4];
    const float* bq = (const float*)d_in[5];
    const float* Wk = (const float*)d_in[6];
    const float* bk = (const float*)d_in[7];
    const float* Wv = (const float*)d_in[8];
    const float* bv = (const float*)d_in[9];
    const float* Wo = (const float*)d_in[10];
    const float* bo = (const float*)d_in[11];
    float* out = (float*)d_out;

    dim3 gGemm(4, 64);
    sgemm_kernel<0><<<gGemm, 256>>>(q, Wq, bq, nullptr);
    sgemm_kernel<1><<<gGemm, 256>>>(k, Wk, bk, nullptr);
    sgemm_kernel<2><<<gGemm, 256>>>(v, Wv, bv, nullptr);

    qk_kernel<<<dim3(8, 8, 128), 256>>>();
    area_softmax_kernel<<<dim3(128, 128), 128>>>();
    av_kernel<<<dim3(8, 128), 256>>>();

    sgemm_kernel<3><<<gGemm, 256>>>(nullptr, Wo, bo, out);
}

// round 5
// speedup vs baseline: 1.9559x; 1.9559x over previous
#include <cuda_runtime.h>
#include <cuda_bf16.h>
#include <cstdint>

// ---------------------------------------------------------------------------
// MultiHeadAreaAttention, all matmuls on mma.sync bf16 (split hi/lo, fp32 acc)
//   x = hi(x) + lo(x) (bf16); X@W ~= Xhi@Whi + Xlo@Whi + Xhi@Wlo
//   realized as K-extended GEMM with operands stored compactly as [hi|lo]
// ---------------------------------------------------------------------------

#define BH_ 128
#define L_  512

// split-bf16 operand buffers (width 1024 = [hi(512) | lo(512)])
__device__ __nv_bfloat16 g_Aq[(size_t)8192 * 1024];
__device__ __nv_bfloat16 g_Ak[(size_t)8192 * 1024];
__device__ __nv_bfloat16 g_Av[(size_t)8192 * 1024];
__device__ __nv_bfloat16 g_Aat[(size_t)8192 * 1024];   // attn rows, written by av
__device__ __nv_bfloat16 g_Bq[512 * 1024];
__device__ __nv_bfloat16 g_Bk[512 * 1024];
__device__ __nv_bfloat16 g_Bv[512 * 1024];
__device__ __nv_bfloat16 g_Bo[512 * 1024];

__device__ __nv_bfloat16 g_Qs[(size_t)BH_ * 512 * 128];  // [bh][l][hi64|lo64]
__device__ __nv_bfloat16 g_Ks[(size_t)BH_ * 512 * 128];
__device__ float         g_Vh[(size_t)BH_ * 512 * 64];   // fp32 V heads
__device__ __nv_bfloat16 g_Vt[(size_t)BH_ * 64 * 1024];  // V^T split [bh][d][hi512|lo512]
__device__ float         g_S[(size_t)BH_ * 512 * 512];   // scores fp32
__device__ __nv_bfloat16 g_Gs[(size_t)BH_ * 512 * 1024]; // G split [bh][t][hi512|lo512]

// ---------------------------------------------------------------------------
static __device__ __forceinline__ uint32_t smem_u32(const void* p) {
    uint32_t a;
    asm("{ .reg .u64 t; cvta.to.shared.u64 t, %1; cvt.u32.u64 %0, t; }"
        : "=r"(a) : "l"(p));
    return a;
}
static __device__ __forceinline__ void ldsm4(uint32_t* r, uint32_t a) {
    asm volatile("ldmatrix.sync.aligned.m8n8.x4.shared.b16 {%0,%1,%2,%3}, [%4];"
                 : "=r"(r[0]), "=r"(r[1]), "=r"(r[2]), "=r"(r[3]) : "r"(a));
}
static __device__ __forceinline__ void mma_bf16(float* d, const uint32_t* a,
                                                uint32_t b0, uint32_t b1) {
    asm volatile(
        "mma.sync.aligned.m16n8k16.row.col.f32.bf16.bf16.f32 "
        "{%0,%1,%2,%3},{%4,%5,%6,%7},{%8,%9},{%0,%1,%2,%3};"
        : "+f"(d[0]), "+f"(d[1]), "+f"(d[2]), "+f"(d[3])
        : "r"(a[0]), "r"(a[1]), "r"(a[2]), "r"(a[3]), "r"(b0), "r"(b1));
}

// ---------------------------------------------------------------------------
// fp32 -> split bf16 conversions
// ---------------------------------------------------------------------------
template <int DST>
__global__ __launch_bounds__(256) void convX(const float* __restrict__ X)
{
    __nv_bfloat16* A = (DST == 0) ? g_Aq : (DST == 1) ? g_Ak : g_Av;
    size_t i4 = (size_t)blockIdx.x * 256 + threadIdx.x;  // 8192*128 float4 groups
    size_t r = i4 >> 7;
    int kq = (int)(i4 & 127) * 4;
    float4 x = *(const float4*)(X + r * 512 + kq);
    __nv_bfloat16 h0 = __float2bfloat16(x.x), h1 = __float2bfloat16(x.y);
    __nv_bfloat16 h2 = __float2bfloat16(x.z), h3 = __float2bfloat16(x.w);
    __nv_bfloat16 l0 = __float2bfloat16(x.x - __bfloat162float(h0));
    __nv_bfloat16 l1 = __float2bfloat16(x.y - __bfloat162float(h1));
    __nv_bfloat16 l2 = __float2bfloat16(x.z - __bfloat162float(h2));
    __nv_bfloat16 l3 = __float2bfloat16(x.w - __bfloat162float(h3));
    __nv_bfloat162* p0 = (__nv_bfloat162*)(A + r * 1024 + kq);
    __nv_bfloat162* p1 = (__nv_bfloat162*)(A + r * 1024 + 512 + kq);
    p0[0] = __halves2bfloat162(h0, h1);
    p0[1] = __halves2bfloat162(h2, h3);
    p1[0] = __halves2bfloat162(l0, l1);
    p1[1] = __halves2bfloat162(l2, l3);
}

template <int DST>
__global__ __launch_bounds__(256) void convW(const float* __restrict__ W)
{
    __nv_bfloat16* Bp = (DST == 0) ? g_Bq : (DST == 1) ? g_Bk : (DST == 2) ? g_Bv : g_Bo;
    int idx = blockIdx.x * 256 + threadIdx.x;  // 512*512
    int n = idx & 511, k = idx >> 9;
    float w = W[(size_t)k * 512 + n];          // transpose: B[n][k] = W[k][n]
    __nv_bfloat16 h = __float2bfloat16(w);
    __nv_bfloat16 l = __float2bfloat16(w - __bfloat162float(h));
    Bp[(size_t)n * 1024 + k]       = h;
    Bp[(size_t)n * 1024 + 512 + k] = l;
}

// ---------------------------------------------------------------------------
// Epilogue dispatch for the dense GEMM
// ---------------------------------------------------------------------------
template <int MODE>
static __device__ __forceinline__ void epi(int r, int c, float v0, float v1,
                                           float* __restrict__ Y)
{
    if (MODE == 3) {
        *(float2*)(Y + (size_t)r * 512 + c) = make_float2(v0, v1);
        return;
    }
    int bh = ((r >> 9) << 3) + (c >> 6), l = r & 511, d = c & 63;
    if (MODE == 2) {
        *(float2*)(g_Vh + ((size_t)bh * 512 + l) * 64 + d) = make_float2(v0, v1);
        return;
    }
    __nv_bfloat16 h0 = __float2bfloat16(v0), h1 = __float2bfloat16(v1);
    __nv_bfloat16 l0 = __float2bfloat16(v0 - __bfloat162float(h0));
    __nv_bfloat16 l1 = __float2bfloat16(v1 - __bfloat162float(h1));
    __nv_bfloat16* dst = ((MODE == 0) ? g_Qs : g_Ks) + ((size_t)bh * 512 + l) * 128 + d;
    *(__nv_bfloat162*)dst        = __halves2bfloat162(h0, h1);
    *(__nv_bfloat162*)(dst + 64) = __halves2bfloat162(l0, l1);
}

// ---------------------------------------------------------------------------
// Dense GEMM on mma.sync: D[8192,512] = split(X)[8192,(1536)] @ split(W)
// A chunks c(0..47): src = c<32 ? c : c-32 ;  B chunks: src = c<16 ? c : c-16
// ---------------------------------------------------------------------------
template <int MODE>
__global__ __launch_bounds__(256) void mma_gemm(const float* __restrict__ bias,
                                                float* __restrict__ Y)
{
    const __nv_bfloat16* A  = (MODE == 0) ? g_Aq : (MODE == 1) ? g_Ak
                             : (MODE == 2) ? g_Av : g_Aat;
    const __nv_bfloat16* Bp = (MODE == 0) ? g_Bq : (MODE == 1) ? g_Bk
                             : (MODE == 2) ? g_Bv : g_Bo;
    __shared__ __nv_bfloat16 sA[2][128 * 40];
    __shared__ __nv_bfloat16 sB[2][128 * 40];
    const int tid = threadIdx.x, lane = tid & 31, wid = tid >> 5;
    const int wx = wid & 1, wy = wid >> 1;
    const int row0 = blockIdx.y * 128, col0 = blockIdx.x * 128;
    const int rL0 = tid >> 2, cL0 = (tid & 3) * 8;
    const int rL1 = rL0 + 64;

    uint32_t sAu = smem_u32(sA), sBu = smem_u32(sB);
    uint32_t aBase = sAu + (((wy * 32 + (lane & 15)) * 40 + ((lane >> 4) << 3)) << 1);
    uint32_t bBase = sBu + (((wx * 64 + ((lane >> 4) << 3) + (lane & 7)) * 40 + (lane & 8)) << 1);

    float acc[2][8][4];
#pragma unroll
    for (int i = 0; i < 2; i++)
#pragma unroll
        for (int j = 0; j < 8; j++)
#pragma unroll
            for (int q = 0; q < 4; q++) acc[i][j][q] = 0.f;

    uint4 pa0, pa1, pb0, pb1;
#define LDT_D(cc)                                                                 \
    {                                                                             \
        int ka = ((cc) < 32 ? (cc) : (cc) - 32) * 32;                             \
        int kb = ((cc) < 16 ? (cc) : (cc) - 16) * 32;                             \
        pa0 = *(const uint4*)(A + (size_t)(row0 + rL0) * 1024 + ka + cL0);        \
        pa1 = *(const uint4*)(A + (size_t)(row0 + rL1) * 1024 + ka + cL0);        \
        pb0 = *(const uint4*)(Bp + (size_t)(col0 + rL0) * 1024 + kb + cL0);       \
        pb1 = *(const uint4*)(Bp + (size_t)(col0 + rL1) * 1024 + kb + cL0);       \
    }
#define STT_D(b)                                                                  \
    {                                                                             \
        *(uint4*)&sA[b][rL0 * 40 + cL0] = pa0;                                    \
        *(uint4*)&sA[b][rL1 * 40 + cL0] = pa1;                                    \
        *(uint4*)&sB[b][rL0 * 40 + cL0] = pb0;                                    \
        *(uint4*)&sB[b][rL1 * 40 + cL0] = pb1;                                    \
    }

    LDT_D(0); STT_D(0); __syncthreads();
    for (int c = 0; c < 48; c++) {
        int b = c & 1;
        if (c < 47) LDT_D(c + 1);
        uint32_t af[2][2][4], bfr[4][2][4];
        uint32_t aB = aBase + b * 10240, bB = bBase + b * 10240;
#pragma unroll
        for (int mi = 0; mi < 2; mi++)
#pragma unroll
            for (int ks = 0; ks < 2; ks++) ldsm4(af[mi][ks], aB + mi * 1280 + ks * 32);
#pragma unroll
        for (int ng = 0; ng < 4; ng++)
#pragma unroll
            for (int ks = 0; ks < 2; ks++) ldsm4(bfr[ng][ks], bB + ng * 1280 + ks * 32);
#pragma unroll
        for (int ks = 0; ks < 2; ks++)
#pragma unroll
            for (int mi = 0; mi < 2; mi++)
#pragma unroll
                for (int ni = 0; ni < 8; ni++)
                    mma_bf16(acc[mi][ni], af[mi][ks],
                             bfr[ni >> 1][ks][(ni & 1) * 2],
                             bfr[ni >> 1][ks][(ni & 1) * 2 + 1]);
        if (c < 47) { STT_D(b ^ 1); __syncthreads(); }
    }

#pragma unroll
    for (int mi = 0; mi < 2; mi++)
#pragma unroll
        for (int ni = 0; ni < 8; ni++) {
            int r = row0 + wy * 32 + mi * 16 + (lane >> 2);
            int cc = col0 + wx * 64 + ni * 8 + (lane & 3) * 2;
            float b0 = bias[cc], b1 = bias[cc + 1];
            epi<MODE>(r, cc, acc[mi][ni][0] + b0, acc[mi][ni][1] + b1, Y);
            epi<MODE>(r + 8, cc, acc[mi][ni][2] + b0, acc[mi][ni][3] + b1, Y);
        }
}

// ---------------------------------------------------------------------------
// V transpose: g_Vh [bh][512][64] fp32 -> g_Vt [bh][64][hi512|lo512] bf16
// ---------------------------------------------------------------------------
__global__ __launch_bounds__(256) void vtrans()
{
    int l0 = blockIdx.x * 64, bh = blockIdx.y;
    __shared__ float sm[64][68];
    const float* V = g_Vh + (size_t)bh * 512 * 64;
    int tid = threadIdx.x;
#pragma unroll
    for (int i = 0; i < 4; i++) {
        int idx4 = tid + i * 256;              // 1024 float4s
        int r = idx4 >> 4, c4 = (idx4 & 15) * 4;
        *(float4*)&sm[r][c4] = *(const float4*)(V + (size_t)(l0 + r) * 64 + c4);
    }
    __syncthreads();
    __nv_bfloat16* O = g_Vt + (size_t)bh * 64 * 1024;
#pragma unroll
    for (int i = 0; i < 16; i++) {
        int e = tid + i * 256;                 // 4096 elems
        int d = e >> 6, l = e & 63;
        float v = sm[l][d];
        __nv_bfloat16 h = __float2bfloat16(v);
        __nv_bfloat16 lo = __float2bfloat16(v - __bfloat162float(h));
        O[(size_t)d * 1024 + l0 + l]       = h;
        O[(size_t)d * 1024 + 512 + l0 + l] = lo;
    }
}

// ---------------------------------------------------------------------------
// qk: S = Qs @ Ks^T (split, K=192) per bh, 128x128 tiles, tri skip
// A chunks 0..5: src = c<4 ? c : c-4 ; B chunks: src = c<2 ? c : c-2
// ---------------------------------------------------------------------------
__global__ __launch_bounds__(256) void qk_mma()
{
    int tk = blockIdx.x, tq = blockIdx.y, bh = blockIdx.z;
    if (tk > tq) return;
    const __nv_bfloat16* A  = g_Qs + (size_t)bh * 512 * 128;
    const __nv_bfloat16* Bp = g_Ks + (size_t)bh * 512 * 128;
    __shared__ __nv_bfloat16 sA[2][128 * 40];
    __shared__ __nv_bfloat16 sB[2][128 * 40];
    const int tid = threadIdx.x, lane = tid & 31, wid = tid >> 5;
    const int wx = wid & 1, wy = wid >> 1;
    const int row0 = tq * 128, col0 = tk * 128;
    const int rL0 = tid >> 2, cL0 = (tid & 3) * 8;
    const int rL1 = rL0 + 64;

    uint32_t sAu = smem_u32(sA), sBu = smem_u32(sB);
    uint32_t aBase = sAu + (((wy * 32 + (lane & 15)) * 40 + ((lane >> 4) << 3)) << 1);
    uint32_t bBase = sBu + (((wx * 64 + ((lane >> 4) << 3) + (lane & 7)) * 40 + (lane & 8)) << 1);

    float acc[2][8][4];
#pragma unroll
    for (int i = 0; i < 2; i++)
#pragma unroll
        for (int j = 0; j < 8; j++)
#pragma unroll
            for (int q = 0; q < 4; q++) acc[i][j][q] = 0.f;

    uint4 pa0, pa1, pb0, pb1;
#define LDT_Q(cc)                                                               \
    {                                                                           \
        int ka = ((cc) < 4 ? (cc) : (cc) - 4) * 32;                             \
        int kb = ((cc) < 2 ? (cc) : (cc) - 2) * 32;                             \
        pa0 = *(const uint4*)(A + (size_t)(row0 + rL0) * 128 + ka + cL0);       \
        pa1 = *(const uint4*)(A + (size_t)(row0 + rL1) * 128 + ka + cL0);       \
        pb0 = *(const uint4*)(Bp + (size_t)(col0 + rL0) * 128 + kb + cL0);      \
        pb1 = *(const uint4*)(Bp + (size_t)(col0 + rL1) * 128 + kb + cL0);      \
    }

    LDT_Q(0); STT_D(0); __syncthreads();
    for (int c = 0; c < 6; c++) {
        int b = c & 1;
        if (c < 5) LDT_Q(c + 1);
        uint32_t af[2][2][4], bfr[4][2][4];
        uint32_t aB = aBase + b * 10240, bB = bBase + b * 10240;
#pragma unroll
        for (int mi = 0; mi < 2; mi++)
#pragma unroll
            for (int ks = 0; ks < 2; ks++) ldsm4(af[mi][ks], aB + mi * 1280 + ks * 32);
#pragma unroll
        for (int ng = 0; ng < 4; ng++)
#pragma unroll
            for (int ks = 0; ks < 2; ks++) ldsm4(bfr[ng][ks], bB + ng * 1280 + ks * 32);
#pragma unroll
        for (int ks = 0; ks < 2; ks++)
#pragma unroll
            for (int mi = 0; mi < 2; mi++)
#pragma unroll
                for (int ni = 0; ni < 8; ni++)
                    mma_bf16(acc[mi][ni], af[mi][ks],
                             bfr[ni >> 1][ks][(ni & 1) * 2],
                             bfr[ni >> 1][ks][(ni & 1) * 2 + 1]);
        if (c < 5) { STT_D(b ^ 1); __syncthreads(); }
    }

    float* Smat = g_S + (size_t)bh * 512 * 512;
#pragma unroll
    for (int mi = 0; mi < 2; mi++)
#pragma unroll
        for (int ni = 0; ni < 8; ni++) {
            int r = row0 + wy * 32 + mi * 16 + (lane >> 2);
            int cc = col0 + wx * 64 + ni * 8 + (lane & 3) * 2;
            *(float2*)(Smat + (size_t)r * 512 + cc) =
                make_float2(acc[mi][ni][0], acc[mi][ni][1]);
            *(float2*)(Smat + (size_t)(r + 8) * 512 + cc) =
                make_float2(acc[mi][ni][2], acc[mi][ni][3]);
        }
}

// ---------------------------------------------------------------------------
// Per-row cumsum + area softmax + fold; emits G as split bf16 [hi512|lo512]
// ---------------------------------------------------------------------------
__global__ __launch_bounds__(128) void area_softmax_kernel()
{
    __shared__ float Cb[4][516];
    __shared__ float Tb[4][516];
    __shared__ float Ub[4][516];
    __shared__ float Vb[4][516];

    int wrp = threadIdx.x >> 5;
    int lane = threadIdx.x & 31;
    int t = blockIdx.x * 4 + wrp;
    int bh = blockIdx.y;

    const float* Srow = g_S + ((size_t)bh * L_ + t) * L_;
    __nv_bfloat16* Grow = g_Gs + ((size_t)bh * L_ + t) * 1024;
    float* C = Cb[wrp];
    float* T = Tb[wrp];
    float* U = Ub[wrp];
    float* V = Vb[wrp];

    if (lane == 0) C[0] = 0.f;
    float carry = 0.f;
    int nchunk = (t + 32) >> 5;
    for (int c0 = 0; c0 < nchunk; c0++) {
        int j = c0 * 32 + lane;
        float s = (j <= t) ? Srow[j] : 0.f;
#pragma unroll
        for (int off = 1; off < 32; off <<= 1) {
            float y = __shfl_up_sync(0xffffffffu, s, off);
            if (lane >= off) s += y;
        }
        s += carry;
        C[1 + j] = s;
        carry = __shfl_sync(0xffffffffu, s, 31);
    }
    __syncwarp();

    float m = -1e30f;
    for (int e = lane; e <= t; e += 32) {
        float ce = C[1 + e];
        m = fmaxf(m, ce - C[e]);
        if (e >= 1) m = fmaxf(m, (ce - C[e - 1]) * 0.5f);
        if (e >= 2) m = fmaxf(m, (ce - C[e - 2]) * (1.f / 3.f));
    }
#pragma unroll
    for (int off = 16; off; off >>= 1) m = fmaxf(m, __shfl_xor_sync(0xffffffffu, m, off));

    float sum = 0.f;
    for (int e = lane; e < 512; e += 32) {
        float p1 = 0.f, p2 = 0.f, p3 = 0.f;
        if (e <= t) {
            float ce = C[1 + e];
            p1 = __expf(ce - C[e] - m);
            if (e >= 1) p2 = __expf((ce - C[e - 1]) * 0.5f - m);
            if (e >= 2) p3 = __expf((ce - C[e - 2]) * (1.f / 3.f) - m);
        }
        T[e] = p1 + p2 + p3;
        U[e] = p2 + p3;
        V[e] = p3;
        sum += p1 + p2 + p3;
    }
    if (lane < 2) { T[512 + lane] = 0.f; U[512 + lane] = 0.f; V[512 + lane] = 0.f; }
#pragma unroll
    for (int off = 16; off; off >>= 1) sum += __shfl_xor_sync(0xffffffffu, sum, off);
    float inv = 1.f / sum;
    __syncwarp();

    for (int j = lane; j < 512; j += 32) {
        float g = (j <= t) ? (T[j] + U[j + 1] + V[j + 2]) * inv : 0.f;
        __nv_bfloat16 h = __float2bfloat16(g);
        Grow[j]       = h;
        Grow[512 + j] = __float2bfloat16(g - __bfloat162float(h));
    }
}

// ---------------------------------------------------------------------------
// av: attn = Gsplit @ Vt^T per bh. Block 128(M)x64(N), 4 warps. Tri K skip.
// K' = 3 segs x (visible j); A seg src: seg==1 ? lo : hi; B: seg==2 ? lo : hi
// Epilogue writes split-bf16 attn rows into g_Aat [b*512+t][hi|lo].
// ---------------------------------------------------------------------------
__global__ __launch_bounds__(128) void av_mma()
{
    int tm = blockIdx.x, bh = blockIdx.y;
    const __nv_bfloat16* A  = g_Gs + (size_t)bh * 512 * 1024;
    const __nv_bfloat16* Bp = g_Vt + (size_t)bh * 64 * 1024;
    __shared__ __nv_bfloat16 sA[2][128 * 40];
    __shared__ __nv_bfloat16 sB[2][64 * 40];
    const int tid = threadIdx.x, lane = tid & 31, wy = tid >> 5;
    const int row0 = tm * 128;
    const int rA = tid >> 2, cA = (tid & 3) * 8;

    uint32_t sAu = smem_u32(sA), sBu = smem_u32(sB);
    uint32_t aBase = sAu + (((wy * 32 + (lane & 15)) * 40 + ((lane >> 4) << 3)) << 1);
    uint32_t bBase = sBu + (((((lane >> 4) << 3) + (lane & 7)) * 40 + (lane & 8)) << 1);

    float acc[2][8][4];
#pragma unroll
    for (int i = 0; i < 2; i++)
#pragma unroll
        for (int j = 0; j < 8; j++)
#pragma unroll
            for (int q = 0; q < 4; q++) acc[i][j][q] = 0.f;

    uint4 pa[4], pb[2];
#define LDT_A(sg, jc)                                                               \
    {                                                                               \
        int ka = ((sg) == 1 ? 512 : 0) + (jc) * 32;                                 \
        int kb = ((sg) == 2 ? 512 : 0) + (jc) * 32;                                 \
        _Pragma("unroll") for (int i = 0; i < 4; i++)                               \
            pa[i] = *(const uint4*)(A + (size_t)(row0 + rA + i * 32) * 1024 + ka + cA); \
        _Pragma("unroll") for (int i = 0; i < 2; i++)                               \
            pb[i] = *(const uint4*)(Bp + (size_t)(rA + i * 32) * 1024 + kb + cA);   \
    }
#define STT_A(b)                                                                    \
    {                                                                               \
        _Pragma("unroll") for (int i = 0; i < 4; i++)                               \
            *(uint4*)&sA[b][(rA + i * 32) * 40 + cA] = pa[i];                       \
        _Pragma("unroll") for (int i = 0; i < 2; i++)                               \
            *(uint4*)&sB[b][(rA + i * 32) * 40 + cA] = pb[i];                       \
    }

    int nj = (tm + 1) * 4, tot = nj * 3;
    int seg = 0, jc = 0;
    LDT_A(0, 0); STT_A(0); __syncthreads();
    for (int it = 0; it < tot; it++) {
        int b = it & 1;
        int ns = seg, njc = jc + 1;
        if (njc == nj) { njc = 0; ns++; }
        if (it < tot - 1) LDT_A(ns, njc);
        uint32_t af[2][2][4], bfr[4][2][4];
        uint32_t aB = aBase + b * 10240, bB = bBase + b * 5120;
#pragma unroll
        for (int mi = 0; mi < 2; mi++)
#pragma unroll
            for (int ks = 0; ks < 2; ks++) ldsm4(af[mi][ks], aB + mi * 1280 + ks * 32);
#pragma unroll
        for (int ng = 0; ng < 4; ng++)
#pragma unroll
            for (int ks = 0; ks < 2; ks++) ldsm4(bfr[ng][ks], bB + ng * 1280 + ks * 32);
#pragma unroll
        for (int ks = 0; ks < 2; ks++)
#pragma unroll
            for (int mi = 0; mi < 2; mi++)
#pragma unroll
                for (int ni = 0; ni < 8; ni++)
                    mma_bf16(acc[mi][ni], af[mi][ks],
                             bfr[ni >> 1][ks][(ni & 1) * 2],
                             bfr[ni >> 1][ks][(ni & 1) * 2 + 1]);
        if (it < tot - 1) { STT_A(b ^ 1); __syncthreads(); }
        seg = ns; jc = njc;
    }

    int b_ = bh >> 3, h_ = bh & 7;
#pragma unroll
    for (int mi = 0; mi < 2; mi++)
#pragma unroll
        for (int ni = 0; ni < 8; ni++) {
            int t0 = row0 + wy * 32 + mi * 16 + (lane >> 2);
            int d = ni * 8 + (lane & 3) * 2;
#pragma unroll
            for (int half = 0; half < 2; half++) {
                int t = t0 + half * 8;
                float v0 = acc[mi][ni][half * 2], v1 = acc[mi][ni][half * 2 + 1];
                __nv_bfloat16 h0 = __float2bfloat16(v0), h1 = __float2bfloat16(v1);
                __nv_bfloat16 l0 = __float2bfloat16(v0 - __bfloat162float(h0));
                __nv_bfloat16 l1 = __float2bfloat16(v1 - __bfloat162float(h1));
                __nv_bfloat16* dst =
                    g_Aat + ((size_t)(b_ * 512 + t)) * 1024 + h_ * 64 + d;
                *(__nv_bfloat162*)dst         = __halves2bfloat162(h0, h1);
                *(__nv_bfloat162*)(dst + 512) = __halves2bfloat162(l0, l1);
            }
        }
}

// ---------------------------------------------------------------------------
extern "C" void kernel_launch(void* const* d_in, const int* in_sizes, int n_in,
                              void* d_out, int out_size)
{
    const float* q  = (const float*)d_in[0];
    const float* k  = (const float*)d_in[1];
    const float* v  = (const float*)d_in[2];
    // d_in[3] = attn_mask — analytic (area end <= t), unused.
    const float* Wq = (const float*)d_in[4];
    const float* bq = (const float*)d_in[5];
    const float* Wk = (const float*)d_in[6];
    const float* bk = (const float*)d_in[7];
    const float* Wv = (const float*)d_in[8];
    const float* bv = (const float*)d_in[9];
    const float* Wo = (const float*)d_in[10];
    const float* bo = (const float*)d_in[11];
    float* out = (float*)d_out;

    convW<0><<<1024, 256>>>(Wq);
    convW<1><<<1024, 256>>>(Wk);
    convW<2><<<1024, 256>>>(Wv);
    convW<3><<<1024, 256>>>(Wo);
    convX<0><<<4096, 256>>>(q);
    convX<1><<<4096, 256>>>(k);
    convX<2><<<4096, 256>>>(v);

    dim3 gG(4, 64);
    mma_gemm<0><<<gG, 256>>>(bq, nullptr);
    mma_gemm<1><<<gG, 256>>>(bk, nullptr);
    mma_gemm<2><<<gG, 256>>>(bv, nullptr);

    vtrans<<<dim3(8, 128), 256>>>();
    qk_mma<<<dim3(4, 4, 128), 256>>>();
    area_softmax_kernel<<<dim3(128, 128), 128>>>();
    av_mma<<<dim3(4, 128), 128>>>();

    mma_gemm<3><<<gG, 256>>>(bo, out);
}

// round 7
// speedup vs baseline: 2.3848x; 1.2193x over previous
#include <cuda_runtime.h>
#include <cuda_bf16.h>
#include <cstdint>

// ---------------------------------------------------------------------------
// MultiHeadAreaAttention, all matmuls on mma.sync bf16 (split hi/lo, fp32 acc)
//   x = hi(x) + lo(x) (bf16); X@W ~= Xhi@Whi + Xlo@Whi + Xhi@Wlo
// Round 7: R6 pipeline (64x64 warp tiles, panel-reuse, cp.async) with the
// static-guard rule violation removed.
// ---------------------------------------------------------------------------

#define BH_ 128
#define L_  512
typedef __nv_bfloat16 bf16;

// split-bf16 operand buffers (width 1024 = [hi(512) | lo(512)])
__device__ bf16 g_Aq[(size_t)8192 * 1024];
__device__ bf16 g_Ak[(size_t)8192 * 1024];
__device__ bf16 g_Av[(size_t)8192 * 1024];
__device__ bf16 g_Aat[(size_t)8192 * 1024];   // attn rows, written by av
__device__ bf16 g_Bq[512 * 1024];
__device__ bf16 g_Bk[512 * 1024];
__device__ bf16 g_Bv[512 * 1024];
__device__ bf16 g_Bo[512 * 1024];

__device__ bf16  g_Qs[(size_t)BH_ * 512 * 128];  // [bh][l][hi64|lo64]
__device__ bf16  g_Ks[(size_t)BH_ * 512 * 128];
__device__ float g_Vh[(size_t)BH_ * 512 * 64];   // fp32 V heads
__device__ bf16  g_Vt[(size_t)BH_ * 64 * 1024];  // V^T split [bh][d][hi512|lo512]
__device__ float g_S[(size_t)BH_ * 512 * 512];   // scores fp32
__device__ bf16  g_Gs[(size_t)BH_ * 512 * 1024]; // G split [bh][t][hi512|lo512]

// ---------------------------------------------------------------------------
static __device__ __forceinline__ uint32_t smem_u32(const void* p) {
    uint32_t a;
    asm("{ .reg .u64 t; cvta.to.shared.u64 t, %1; cvt.u32.u64 %0, t; }"
        : "=r"(a) : "l"(p));
    return a;
}
static __device__ __forceinline__ void ldsm4(uint32_t* r, uint32_t a) {
    asm volatile("ldmatrix.sync.aligned.m8n8.x4.shared.b16 {%0,%1,%2,%3}, [%4];"
                 : "=r"(r[0]), "=r"(r[1]), "=r"(r[2]), "=r"(r[3]) : "r"(a));
}
static __device__ __forceinline__ void mma_bf16(float* d, const uint32_t* a,
                                                uint32_t b0, uint32_t b1) {
    asm volatile(
        "mma.sync.aligned.m16n8k16.row.col.f32.bf16.bf16.f32 "
        "{%0,%1,%2,%3},{%4,%5,%6,%7},{%8,%9},{%0,%1,%2,%3};"
        : "+f"(d[0]), "+f"(d[1]), "+f"(d[2]), "+f"(d[3])
        : "r"(a[0]), "r"(a[1]), "r"(a[2]), "r"(a[3]), "r"(b0), "r"(b1));
}
#define CP16(dst, src)                                                         \
    asm volatile("cp.async.cg.shared.global [%0], [%1], 16;" ::"r"(dst),       \
                 "l"(src))
#define CP_COMMIT() asm volatile("cp.async.commit_group;")
#define CP_WAIT(n) asm volatile("cp.async.wait_group %0;" ::"n"(n))

// ---------------------------------------------------------------------------
// fused fp32 -> split bf16 conversions
// ---------------------------------------------------------------------------
__global__ __launch_bounds__(256) void convX_all(const float* __restrict__ q,
                                                 const float* __restrict__ k,
                                                 const float* __restrict__ v)
{
    int z = blockIdx.z;
    const float* X = (z == 0) ? q : (z == 1) ? k : v;
    bf16* A = (z == 0) ? g_Aq : (z == 1) ? g_Ak : g_Av;
    size_t i4 = (size_t)blockIdx.x * 256 + threadIdx.x;  // 8192*128 float4 groups
    size_t r = i4 >> 7;
    int kq = (int)(i4 & 127) * 4;
    float4 x = *(const float4*)(X + r * 512 + kq);
    bf16 h0 = __float2bfloat16(x.x), h1 = __float2bfloat16(x.y);
    bf16 h2 = __float2bfloat16(x.z), h3 = __float2bfloat16(x.w);
    bf16 l0 = __float2bfloat16(x.x - __bfloat162float(h0));
    bf16 l1 = __float2bfloat16(x.y - __bfloat162float(h1));
    bf16 l2 = __float2bfloat16(x.z - __bfloat162float(h2));
    bf16 l3 = __float2bfloat16(x.w - __bfloat162float(h3));
    __nv_bfloat162* p0 = (__nv_bfloat162*)(A + r * 1024 + kq);
    __nv_bfloat162* p1 = (__nv_bfloat162*)(A + r * 1024 + 512 + kq);
    p0[0] = __halves2bfloat162(h0, h1);
    p0[1] = __halves2bfloat162(h2, h3);
    p1[0] = __halves2bfloat162(l0, l1);
    p1[1] = __halves2bfloat162(l2, l3);
}

__global__ __launch_bounds__(256) void convW_all(const float* __restrict__ Wq,
                                                 const float* __restrict__ Wk,
                                                 const float* __restrict__ Wv,
                                                 const float* __restrict__ Wo)
{
    __shared__ float t[32][33];
    int z = blockIdx.z;
    const float* W = (z == 0) ? Wq : (z == 1) ? Wk : (z == 2) ? Wv : Wo;
    bf16* Bp = (z == 0) ? g_Bq : (z == 1) ? g_Bk : (z == 2) ? g_Bv : g_Bo;
    int n0 = blockIdx.x * 32, k0 = blockIdx.y * 32;
    int tx = threadIdx.x & 31, ty = threadIdx.x >> 5;  // 32 x 8
#pragma unroll
    for (int i = 0; i < 4; i++)
        t[ty + i * 8][tx] = W[(size_t)(k0 + ty + i * 8) * 512 + n0 + tx];
    __syncthreads();
#pragma unroll
    for (int i = 0; i < 4; i++) {
        int n = n0 + ty + i * 8, k = k0 + tx;
        float w = t[tx][ty + i * 8];
        bf16 h = __float2bfloat16(w);
        bf16 l = __float2bfloat16(w - __bfloat162float(h));
        Bp[(size_t)n * 1024 + k]       = h;
        Bp[(size_t)n * 1024 + 512 + k] = l;
    }
}

// ---------------------------------------------------------------------------
// Epilogue dispatch for the dense GEMM
// ---------------------------------------------------------------------------
template <int MODE>
static __device__ __forceinline__ void epi(int r, int c, float v0, float v1,
                                           float* __restrict__ Y)
{
    if (MODE == 3) {
        *(float2*)(Y + (size_t)r * 512 + c) = make_float2(v0, v1);
        return;
    }
    int bh = ((r >> 9) << 3) + (c >> 6), l = r & 511, d = c & 63;
    if (MODE == 2) {
        *(float2*)(g_Vh + ((size_t)bh * 512 + l) * 64 + d) = make_float2(v0, v1);
        return;
    }
    bf16 h0 = __float2bfloat16(v0), h1 = __float2bfloat16(v1);
    bf16 l0 = __float2bfloat16(v0 - __bfloat162float(h0));
    bf16 l1 = __float2bfloat16(v1 - __bfloat162float(h1));
    bf16* dst = ((MODE == 0) ? g_Qs : g_Ks) + ((size_t)bh * 512 + l) * 128 + d;
    *(__nv_bfloat162*)dst        = __halves2bfloat162(h0, h1);
    *(__nv_bfloat162*)(dst + 64) = __halves2bfloat162(l0, l1);
}

// ---------------------------------------------------------------------------
// Dense GEMM v2: D[8192,512] = split(X) @ split(W); 4 warps of 64x64.
// Per k32 chunk: stage Ah/Al/Bh/Bl panels; terms AhBh + AlBh + AhBl.
// Dynamic smem: 2 stages x 4 panels x 10240B = 81920.
// ---------------------------------------------------------------------------
#define PANEL 10240
#define STAGE 40960

template <int MODE>
__global__ __launch_bounds__(128) void mma_gemm(const float* __restrict__ bias,
                                                float* __restrict__ Y)
{
    const bf16* A  = (MODE == 0) ? g_Aq : (MODE == 1) ? g_Ak
                    : (MODE == 2) ? g_Av : g_Aat;
    const bf16* Bp = (MODE == 0) ? g_Bq : (MODE == 1) ? g_Bk
                    : (MODE == 2) ? g_Bv : g_Bo;
    extern __shared__ char sm[];
    uint32_t sb = smem_u32(sm);
    const int tid = threadIdx.x, lane = tid & 31, wid = tid >> 5;
    const int wy = wid >> 1, wx = wid & 1;
    const int row0 = blockIdx.y * 128, col0 = blockIdx.x * 128;

    const uint32_t aOff = ((wy * 64 + (lane & 15)) * 40 + ((lane >> 4) << 3)) * 2;
    const uint32_t bOff =
        ((wx * 64 + ((lane >> 4) << 3) + (lane & 7)) * 40 + (lane & 8)) * 2;

    float acc[4][8][4];
#pragma unroll
    for (int i = 0; i < 4; i++)
#pragma unroll
        for (int j = 0; j < 8; j++)
#pragma unroll
            for (int q = 0; q < 4; q++) acc[i][j][q] = 0.f;

#define FILL_D(kk, st)                                                          \
    {                                                                           \
        uint32_t stb = sb + (st)*STAGE;                                         \
        _Pragma("unroll") for (int i = 0; i < 4; i++)                           \
        {                                                                       \
            int s = tid + i * 128;                                              \
            int r = s >> 2, c = s & 3;                                          \
            uint32_t off = (uint32_t)(r * 40 + c * 8) * 2;                      \
            const bf16* a0 = A + (size_t)(row0 + r) * 1024 + (kk)*32 + c * 8;   \
            const bf16* b0 = Bp + (size_t)(col0 + r) * 1024 + (kk)*32 + c * 8;  \
            CP16(stb + off, a0);                                                \
            CP16(stb + PANEL + off, a0 + 512);                                  \
            CP16(stb + 2 * PANEL + off, b0);                                    \
            CP16(stb + 3 * PANEL + off, b0 + 512);                              \
        }                                                                       \
        CP_COMMIT();                                                            \
    }

    FILL_D(0, 0);
    FILL_D(1, 1);
    for (int kk = 0; kk < 16; kk++) {
        if (kk < 15) CP_WAIT(1); else CP_WAIT(0);
        __syncthreads();
        uint32_t stb = sb + (kk & 1) * STAGE;
#pragma unroll
        for (int ks = 0; ks < 2; ks++) {
            uint32_t ah[4][4], al[4][4], bh[4][4], bl[4][4];
#pragma unroll
            for (int mi = 0; mi < 4; mi++) {
                ldsm4(ah[mi], stb + aOff + mi * 1280 + ks * 32);
                ldsm4(al[mi], stb + PANEL + aOff + mi * 1280 + ks * 32);
            }
#pragma unroll
            for (int ng = 0; ng < 4; ng++) {
                ldsm4(bh[ng], stb + 2 * PANEL + bOff + ng * 1280 + ks * 32);
                ldsm4(bl[ng], stb + 3 * PANEL + bOff + ng * 1280 + ks * 32);
            }
#pragma unroll
            for (int mi = 0; mi < 4; mi++)
#pragma unroll
                for (int ni = 0; ni < 8; ni++) {
                    uint32_t bh0 = bh[ni >> 1][(ni & 1) * 2];
                    uint32_t bh1 = bh[ni >> 1][(ni & 1) * 2 + 1];
                    mma_bf16(acc[mi][ni], ah[mi], bh0, bh1);
                    mma_bf16(acc[mi][ni], al[mi], bh0, bh1);
                    mma_bf16(acc[mi][ni], ah[mi],
                             bl[ni >> 1][(ni & 1) * 2],
                             bl[ni >> 1][(ni & 1) * 2 + 1]);
                }
        }
        __syncthreads();
        if (kk + 2 < 16) FILL_D(kk + 2, kk & 1);
    }

#pragma unroll
    for (int mi = 0; mi < 4; mi++)
#pragma unroll
        for (int ni = 0; ni < 8; ni++) {
            int r = row0 + wy * 64 + mi * 16 + (lane >> 2);
            int cc = col0 + wx * 64 + ni * 8 + (lane & 3) * 2;
            float b0 = __ldg(&bias[cc]), b1 = __ldg(&bias[cc + 1]);
            epi<MODE>(r, cc, acc[mi][ni][0] + b0, acc[mi][ni][1] + b1, Y);
            epi<MODE>(r + 8, cc, acc[mi][ni][2] + b0, acc[mi][ni][3] + b1, Y);
        }
}

// ---------------------------------------------------------------------------
// V transpose: g_Vh [bh][512][64] fp32 -> g_Vt [bh][64][hi512|lo512] bf16
// ---------------------------------------------------------------------------
__global__ __launch_bounds__(256) void vtrans()
{
    int l0 = blockIdx.x * 64, bh = blockIdx.y;
    __shared__ float sm[64][68];
    const float* V = g_Vh + (size_t)bh * 512 * 64;
    int tid = threadIdx.x;
#pragma unroll
    for (int i = 0; i < 4; i++) {
        int idx4 = tid + i * 256;
        int r = idx4 >> 4, c4 = (idx4 & 15) * 4;
        *(float4*)&sm[r][c4] = *(const float4*)(V + (size_t)(l0 + r) * 64 + c4);
    }
    __syncthreads();
    bf16* O = g_Vt + (size_t)bh * 64 * 1024;
#pragma unroll
    for (int i = 0; i < 16; i++) {
        int e = tid + i * 256;
        int d = e >> 6, l = e & 63;
        float v = sm[l][d];
        bf16 h = __float2bfloat16(v);
        bf16 lo = __float2bfloat16(v - __bfloat162float(h));
        O[(size_t)d * 1024 + l0 + l]       = h;
        O[(size_t)d * 1024 + 512 + l0 + l] = lo;
    }
}

// ---------------------------------------------------------------------------
// qk v2: S = Qs @ Ks^T per bh. 4 warps of 64x64; whole split-K resident.
// Panels: Q {hi k0, hi k1, lo k0, lo k1} then K same; 8 x 10240B = 81920.
// ---------------------------------------------------------------------------
__global__ __launch_bounds__(128) void qk_mma()
{
    int tk = blockIdx.x, tq = blockIdx.y, bh = blockIdx.z;
    if (tk > tq) return;
    const bf16* Aq = g_Qs + (size_t)bh * 512 * 128;
    const bf16* Bk = g_Ks + (size_t)bh * 512 * 128;
    extern __shared__ char sm[];
    uint32_t sb = smem_u32(sm);
    const int tid = threadIdx.x, lane = tid & 31, wid = tid >> 5;
    const int wy = wid >> 1, wx = wid & 1;
    const int row0 = tq * 128, col0 = tk * 128;

    const uint32_t aOff = ((wy * 64 + (lane & 15)) * 40 + ((lane >> 4) << 3)) * 2;
    const uint32_t bOff =
        ((wx * 64 + ((lane >> 4) << 3) + (lane & 7)) * 40 + (lane & 8)) * 2;

#pragma unroll
    for (int p = 0; p < 4; p++) {  // p = part*2 + kk
        int part = p >> 1, kk = p & 1;
        int colb = part * 64 + kk * 32;
#pragma unroll
        for (int i = 0; i < 4; i++) {
            int s = tid + i * 128;
            int r = s >> 2, c = s & 3;
            uint32_t off = (uint32_t)(r * 40 + c * 8) * 2;
            CP16(sb + p * PANEL + off,
                 Aq + (size_t)(row0 + r) * 128 + colb + c * 8);
            CP16(sb + (4 + p) * PANEL + off,
                 Bk + (size_t)(col0 + r) * 128 + colb + c * 8);
        }
    }
    CP_COMMIT();

    float acc[4][8][4];
#pragma unroll
    for (int i = 0; i < 4; i++)
#pragma unroll
        for (int j = 0; j < 8; j++)
#pragma unroll
            for (int q = 0; q < 4; q++) acc[i][j][q] = 0.f;

    CP_WAIT(0);
    __syncthreads();

#pragma unroll
    for (int kk = 0; kk < 2; kk++) {
        uint32_t qh = sb + kk * PANEL, ql = sb + (2 + kk) * PANEL;
        uint32_t kh = sb + (4 + kk) * PANEL, kl = sb + (6 + kk) * PANEL;
#pragma unroll
        for (int ks = 0; ks < 2; ks++) {
            uint32_t ah[4][4], al[4][4], bh[4][4], bl[4][4];
#pragma unroll
            for (int mi = 0; mi < 4; mi++) {
                ldsm4(ah[mi], qh + aOff + mi * 1280 + ks * 32);
                ldsm4(al[mi], ql + aOff + mi * 1280 + ks * 32);
            }
#pragma unroll
            for (int ng = 0; ng < 4; ng++) {
                ldsm4(bh[ng], kh + bOff + ng * 1280 + ks * 32);
                ldsm4(bl[ng], kl + bOff + ng * 1280 + ks * 32);
            }
#pragma unroll
            for (int mi = 0; mi < 4; mi++)
#pragma unroll
                for (int ni = 0; ni < 8; ni++) {
                    uint32_t bh0 = bh[ni >> 1][(ni & 1) * 2];
                    uint32_t bh1 = bh[ni >> 1][(ni & 1) * 2 + 1];
                    mma_bf16(acc[mi][ni], ah[mi], bh0, bh1);
                    mma_bf16(acc[mi][ni], al[mi], bh0, bh1);
                    mma_bf16(acc[mi][ni], ah[mi],
                             bl[ni >> 1][(ni & 1) * 2],
                             bl[ni >> 1][(ni & 1) * 2 + 1]);
                }
        }
    }

    float* Smat = g_S + (size_t)bh * 512 * 512;
#pragma unroll
    for (int mi = 0; mi < 4; mi++)
#pragma unroll
        for (int ni = 0; ni < 8; ni++) {
            int r = row0 + wy * 64 + mi * 16 + (lane >> 2);
            int cc = col0 + wx * 64 + ni * 8 + (lane & 3) * 2;
            *(float2*)(Smat + (size_t)r * 512 + cc) =
                make_float2(acc[mi][ni][0], acc[mi][ni][1]);
            *(float2*)(Smat + (size_t)(r + 8) * 512 + cc) =
                make_float2(acc[mi][ni][2], acc[mi][ni][3]);
        }
}

// ---------------------------------------------------------------------------
// Per-row cumsum + area softmax + fold; emits G split bf16 up to tile bound.
// ---------------------------------------------------------------------------
__global__ __launch_bounds__(128) void area_softmax_kernel()
{
    __shared__ float Cb[4][516];
    __shared__ float Tb[4][516];
    __shared__ float Ub[4][516];
    __shared__ float Vb[4][516];

    int wrp = threadIdx.x >> 5;
    int lane = threadIdx.x & 31;
    int t = blockIdx.x * 4 + wrp;
    int bh = blockIdx.y;
    int bound = ((t >> 7) + 1) << 7;  // av reads j < bound only

    const float* Srow = g_S + ((size_t)bh * L_ + t) * L_;
    bf16* Grow = g_Gs + ((size_t)bh * L_ + t) * 1024;
    float* C = Cb[wrp];
    float* T = Tb[wrp];
    float* U = Ub[wrp];
    float* V = Vb[wrp];

    if (lane == 0) C[0] = 0.f;
    float carry = 0.f;
    int nchunk = (t + 32) >> 5;
    for (int c0 = 0; c0 < nchunk; c0++) {
        int j = c0 * 32 + lane;
        float s = (j <= t) ? Srow[j] : 0.f;
#pragma unroll
        for (int off = 1; off < 32; off <<= 1) {
            float y = __shfl_up_sync(0xffffffffu, s, off);
            if (lane >= off) s += y;
        }
        s += carry;
        C[1 + j] = s;
        carry = __shfl_sync(0xffffffffu, s, 31);
    }
    __syncwarp();

    float m = -1e30f;
    for (int e = lane; e <= t; e += 32) {
        float ce = C[1 + e];
        m = fmaxf(m, ce - C[e]);
        if (e >= 1) m = fmaxf(m, (ce - C[e - 1]) * 0.5f);
        if (e >= 2) m = fmaxf(m, (ce - C[e - 2]) * (1.f / 3.f));
    }
#pragma unroll
    for (int off = 16; off; off >>= 1) m = fmaxf(m, __shfl_xor_sync(0xffffffffu, m, off));

    // zero pad region (t, bound+2) so fold reads are defined
    for (int e = t + 1 + lane; e < bound + 2; e += 32) {
        T[e] = 0.f; U[e] = 0.f; V[e] = 0.f;
    }

    float sum = 0.f;
    for (int e = lane; e <= t; e += 32) {
        float ce = C[1 + e];
        float p1 = __expf(ce - C[e] - m);
        float p2 = (e >= 1) ? __expf((ce - C[e - 1]) * 0.5f - m) : 0.f;
        float p3 = (e >= 2) ? __expf((ce - C[e - 2]) * (1.f / 3.f) - m) : 0.f;
        T[e] = p1 + p2 + p3;
        U[e] = p2 + p3;
        V[e] = p3;
        sum += p1 + p2 + p3;
    }
#pragma unroll
    for (int off = 16; off; off >>= 1) sum += __shfl_xor_sync(0xffffffffu, sum, off);
    float inv = 1.f / sum;
    __syncwarp();

    for (int j = lane; j < bound; j += 32) {
        float g = (j <= t) ? (T[j] + U[j + 1] + V[j + 2]) * inv : 0.f;
        bf16 h = __float2bfloat16(g);
        Grow[j]       = h;
        Grow[512 + j] = __float2bfloat16(g - __bfloat162float(h));
    }
}

// ---------------------------------------------------------------------------
// av: attn = Gsplit @ Vt^T per bh. Block 128(M)x64(N), 4 warps. Tri K skip.
// ---------------------------------------------------------------------------
__global__ __launch_bounds__(128) void av_mma()
{
    int tm = blockIdx.x, bh = blockIdx.y;
    const bf16* A  = g_Gs + (size_t)bh * 512 * 1024;
    const bf16* Bp = g_Vt + (size_t)bh * 64 * 1024;
    __shared__ bf16 sA[2][128 * 40];
    __shared__ bf16 sB[2][64 * 40];
    const int tid = threadIdx.x, lane = tid & 31, wy = tid >> 5;
    const int row0 = tm * 128;
    const int rA = tid >> 2, cA = (tid & 3) * 8;

    uint32_t sAu = smem_u32(sA), sBu = smem_u32(sB);
    uint32_t aBase = sAu + (((wy * 32 + (lane & 15)) * 40 + ((lane >> 4) << 3)) << 1);
    uint32_t bBase = sBu + (((((lane >> 4) << 3) + (lane & 7)) * 40 + (lane & 8)) << 1);

    float acc[2][8][4];
#pragma unroll
    for (int i = 0; i < 2; i++)
#pragma unroll
        for (int j = 0; j < 8; j++)
#pragma unroll
            for (int q = 0; q < 4; q++) acc[i][j][q] = 0.f;

    uint4 pa[4], pb[2];
#define LDT_A(sg, jc)                                                               \
    {                                                                               \
        int ka = ((sg) == 1 ? 512 : 0) + (jc) * 32;                                 \
        int kb = ((sg) == 2 ? 512 : 0) + (jc) * 32;                                 \
        _Pragma("unroll") for (int i = 0; i < 4; i++)                               \
            pa[i] = *(const uint4*)(A + (size_t)(row0 + rA + i * 32) * 1024 + ka + cA); \
        _Pragma("unroll") for (int i = 0; i < 2; i++)                               \
            pb[i] = *(const uint4*)(Bp + (size_t)(rA + i * 32) * 1024 + kb + cA);   \
    }
#define STT_A(b)                                                                    \
    {                                                                               \
        _Pragma("unroll") for (int i = 0; i < 4; i++)                               \
            *(uint4*)&sA[b][(rA + i * 32) * 40 + cA] = pa[i];                       \
        _Pragma("unroll") for (int i = 0; i < 2; i++)                               \
            *(uint4*)&sB[b][(rA + i * 32) * 40 + cA] = pb[i];                       \
    }

    int nj = (tm + 1) * 4, tot = nj * 3;
    int seg = 0, jc = 0;
    LDT_A(0, 0); STT_A(0); __syncthreads();
    for (int it = 0; it < tot; it++) {
        int b = it & 1;
        int ns = seg, njc = jc + 1;
        if (njc == nj) { njc = 0; ns++; }
        if (it < tot - 1) LDT_A(ns, njc);
        uint32_t af[2][2][4], bfr[4][2][4];
        uint32_t aB = aBase + b * 10240, bB = bBase + b * 5120;
#pragma unroll
        for (int mi = 0; mi < 2; mi++)
#pragma unroll
            for (int ks = 0; ks < 2; ks++) ldsm4(af[mi][ks], aB + mi * 1280 + ks * 32);
#pragma unroll
        for (int ng = 0; ng < 4; ng++)
#pragma unroll
            for (int ks = 0; ks < 2; ks++) ldsm4(bfr[ng][ks], bB + ng * 1280 + ks * 32);
#pragma unroll
        for (int ks = 0; ks < 2; ks++)
#pragma unroll
            for (int mi = 0; mi < 2; mi++)
#pragma unroll
                for (int ni = 0; ni < 8; ni++)
                    mma_bf16(acc[mi][ni], af[mi][ks],
                             bfr[ni >> 1][ks][(ni & 1) * 2],
                             bfr[ni >> 1][ks][(ni & 1) * 2 + 1]);
        if (it < tot - 1) { STT_A(b ^ 1); __syncthreads(); }
        seg = ns; jc = njc;
    }

    int b_ = bh >> 3, h_ = bh & 7;
#pragma unroll
    for (int mi = 0; mi < 2; mi++)
#pragma unroll
        for (int ni = 0; ni < 8; ni++) {
            int t0 = row0 + wy * 32 + mi * 16 + (lane >> 2);
            int d = ni * 8 + (lane & 3) * 2;
#pragma unroll
            for (int half = 0; half < 2; half++) {
                int t = t0 + half * 8;
                float v0 = acc[mi][ni][half * 2], v1 = acc[mi][ni][half * 2 + 1];
                bf16 h0 = __float2bfloat16(v0), h1 = __float2bfloat16(v1);
                bf16 l0 = __float2bfloat16(v0 - __bfloat162float(h0));
                bf16 l1 = __float2bfloat16(v1 - __bfloat162float(h1));
                bf16* dst = g_Aat + ((size_t)(b_ * 512 + t)) * 1024 + h_ * 64 + d;
                *(__nv_bfloat162*)dst         = __halves2bfloat162(h0, h1);
                *(__nv_bfloat162*)(dst + 512) = __halves2bfloat162(l0, l1);
            }
        }
}

// ---------------------------------------------------------------------------
extern "C" void kernel_launch(void* const* d_in, const int* in_sizes, int n_in,
                              void* d_out, int out_size)
{
    const float* q  = (const float*)d_in[0];
    const float* k  = (const float*)d_in[1];
    const float* v  = (const float*)d_in[2];
    // d_in[3] = attn_mask — analytic (area end <= t), unused.
    const float* Wq = (const float*)d_in[4];
    const float* bq = (const float*)d_in[5];
    const float* Wk = (const float*)d_in[6];
    const float* bk = (const float*)d_in[7];
    const float* Wv = (const float*)d_in[8];
    const float* bv = (const float*)d_in[9];
    const float* Wo = (const float*)d_in[10];
    const float* bo = (const float*)d_in[11];
    float* out = (float*)d_out;

    // Host-side, idempotent, not captured into the graph (not a stream op).
    cudaFuncSetAttribute(mma_gemm<0>, cudaFuncAttributeMaxDynamicSharedMemorySize, 81920);
    cudaFuncSetAttribute(mma_gemm<1>, cudaFuncAttributeMaxDynamicSharedMemorySize, 81920);
    cudaFuncSetAttribute(mma_gemm<2>, cudaFuncAttributeMaxDynamicSharedMemorySize, 81920);
    cudaFuncSetAttribute(mma_gemm<3>, cudaFuncAttributeMaxDynamicSharedMemorySize, 81920);
    cudaFuncSetAttribute(qk_mma, cudaFuncAttributeMaxDynamicSharedMemorySize, 81920);

    convW_all<<<dim3(16, 16, 4), 256>>>(Wq, Wk, Wv, Wo);
    convX_all<<<dim3(4096, 1, 3), 256>>>(q, k, v);

    dim3 gG(4, 64);
    mma_gemm<0><<<gG, 128, 81920>>>(bq, nullptr);
    mma_gemm<1><<<gG, 128, 81920>>>(bk, nullptr);
    mma_gemm<2><<<gG, 128, 81920>>>(bv, nullptr);

    vtrans<<<dim3(8, 128), 256>>>();
    qk_mma<<<dim3(4, 4, 128), 128, 81920>>>();
    area_softmax_kernel<<<dim3(128, 128), 128>>>();
    av_mma<<<dim3(4, 128), 128>>>();

    mma_gemm<3><<<gG, 128, 81920>>>(bo, out);
}

// round 8
// speedup vs baseline: 3.0577x; 1.2821x over previous
#include <cuda_runtime.h>
#include <cuda_bf16.h>
#include <cuda_fp16.h>
#include <cstdint>

// ---------------------------------------------------------------------------
// MultiHeadAreaAttention. Precision-tiered tensor-core pipeline:
//   Q/K chain (proj Q, proj K, QK^T): split-bf16 3-term (needs ~1e-4 logits)
//   V path (proj V, G@V, out proj):   single-term fp16 (tolerates ~1e-4 rel)
// ---------------------------------------------------------------------------

#define BH_ 128
#define L_  512
typedef __nv_bfloat16 bf16;

// bf16 split operands for Q/K chain
__device__ bf16 g_Aq[(size_t)8192 * 1024];
__device__ bf16 g_Ak[(size_t)8192 * 1024];
__device__ bf16 g_Bq[512 * 1024];
__device__ bf16 g_Bk[512 * 1024];
__device__ bf16 g_Qs[(size_t)BH_ * 512 * 128];  // [bh][l][hi64|lo64]
__device__ bf16 g_Ks[(size_t)BH_ * 512 * 128];

// fp16 single operands for V path
__device__ __half g_Avh[(size_t)8192 * 512];     // fp16(v)
__device__ __half g_Bvh[512 * 512];              // fp16(Wv)^T  (n-major)
__device__ __half g_Boh[512 * 512];              // fp16(Wo)^T
__device__ __half g_Vth[(size_t)BH_ * 64 * 512]; // V^T per bh
__device__ __half g_Gh[(size_t)BH_ * 512 * 512]; // softmax-folded G
__device__ __half g_Aath[(size_t)8192 * 512];    // attn rows [b*512+t][h*64+d]

__device__ float g_Vh[(size_t)BH_ * 512 * 64];   // fp32 V heads (proj V out)
__device__ float g_S[(size_t)BH_ * 512 * 512];   // scores fp32

// ---------------------------------------------------------------------------
static __device__ __forceinline__ uint32_t smem_u32(const void* p) {
    uint32_t a;
    asm("{ .reg .u64 t; cvta.to.shared.u64 t, %1; cvt.u32.u64 %0, t; }"
        : "=r"(a) : "l"(p));
    return a;
}
static __device__ __forceinline__ void ldsm4(uint32_t* r, uint32_t a) {
    asm volatile("ldmatrix.sync.aligned.m8n8.x4.shared.b16 {%0,%1,%2,%3}, [%4];"
                 : "=r"(r[0]), "=r"(r[1]), "=r"(r[2]), "=r"(r[3]) : "r"(a));
}
static __device__ __forceinline__ void mma_bf16(float* d, const uint32_t* a,
                                                uint32_t b0, uint32_t b1) {
    asm volatile(
        "mma.sync.aligned.m16n8k16.row.col.f32.bf16.bf16.f32 "
        "{%0,%1,%2,%3},{%4,%5,%6,%7},{%8,%9},{%0,%1,%2,%3};"
        : "+f"(d[0]), "+f"(d[1]), "+f"(d[2]), "+f"(d[3])
        : "r"(a[0]), "r"(a[1]), "r"(a[2]), "r"(a[3]), "r"(b0), "r"(b1));
}
static __device__ __forceinline__ void mma_f16(float* d, const uint32_t* a,
                                               uint32_t b0, uint32_t b1) {
    asm volatile(
        "mma.sync.aligned.m16n8k16.row.col.f32.f16.f16.f32 "
        "{%0,%1,%2,%3},{%4,%5,%6,%7},{%8,%9},{%0,%1,%2,%3};"
        : "+f"(d[0]), "+f"(d[1]), "+f"(d[2]), "+f"(d[3])
        : "r"(a[0]), "r"(a[1]), "r"(a[2]), "r"(a[3]), "r"(b0), "r"(b1));
}
#define CP16(dst, src)                                                         \
    asm volatile("cp.async.cg.shared.global [%0], [%1], 16;" ::"r"(dst),       \
                 "l"(src))
#define CP_COMMIT() asm volatile("cp.async.commit_group;")
#define CP_WAIT(n) asm volatile("cp.async.wait_group %0;" ::"n"(n))

// ---------------------------------------------------------------------------
// conversions
// ---------------------------------------------------------------------------
__global__ __launch_bounds__(256) void convX_all(const float* __restrict__ q,
                                                 const float* __restrict__ k)
{
    int z = blockIdx.z;
    const float* X = (z == 0) ? q : k;
    bf16* A = (z == 0) ? g_Aq : g_Ak;
    size_t i4 = (size_t)blockIdx.x * 256 + threadIdx.x;
    size_t r = i4 >> 7;
    int kq = (int)(i4 & 127) * 4;
    float4 x = *(const float4*)(X + r * 512 + kq);
    bf16 h0 = __float2bfloat16(x.x), h1 = __float2bfloat16(x.y);
    bf16 h2 = __float2bfloat16(x.z), h3 = __float2bfloat16(x.w);
    bf16 l0 = __float2bfloat16(x.x - __bfloat162float(h0));
    bf16 l1 = __float2bfloat16(x.y - __bfloat162float(h1));
    bf16 l2 = __float2bfloat16(x.z - __bfloat162float(h2));
    bf16 l3 = __float2bfloat16(x.w - __bfloat162float(h3));
    __nv_bfloat162* p0 = (__nv_bfloat162*)(A + r * 1024 + kq);
    __nv_bfloat162* p1 = (__nv_bfloat162*)(A + r * 1024 + 512 + kq);
    p0[0] = __halves2bfloat162(h0, h1);
    p0[1] = __halves2bfloat162(h2, h3);
    p1[0] = __halves2bfloat162(l0, l1);
    p1[1] = __halves2bfloat162(l2, l3);
}

__global__ __launch_bounds__(256) void convV_h(const float* __restrict__ v)
{
    size_t idx = (size_t)blockIdx.x * 256 + threadIdx.x;  // 1M float4 groups
    float4 x = ((const float4*)v)[idx];
    __half2* p = (__half2*)(g_Avh + idx * 4);
    p[0] = __floats2half2_rn(x.x, x.y);
    p[1] = __floats2half2_rn(x.z, x.w);
}

__global__ __launch_bounds__(256) void convW_all(const float* __restrict__ Wq,
                                                 const float* __restrict__ Wk)
{
    __shared__ float t[32][33];
    int z = blockIdx.z;
    const float* W = (z == 0) ? Wq : Wk;
    bf16* Bp = (z == 0) ? g_Bq : g_Bk;
    int n0 = blockIdx.x * 32, k0 = blockIdx.y * 32;
    int tx = threadIdx.x & 31, ty = threadIdx.x >> 5;
#pragma unroll
    for (int i = 0; i < 4; i++)
        t[ty + i * 8][tx] = W[(size_t)(k0 + ty + i * 8) * 512 + n0 + tx];
    __syncthreads();
#pragma unroll
    for (int i = 0; i < 4; i++) {
        int n = n0 + ty + i * 8, k = k0 + tx;
        float w = t[tx][ty + i * 8];
        bf16 h = __float2bfloat16(w);
        bf16 l = __float2bfloat16(w - __bfloat162float(h));
        Bp[(size_t)n * 1024 + k]       = h;
        Bp[(size_t)n * 1024 + 512 + k] = l;
    }
}

__global__ __launch_bounds__(256) void convW_h(const float* __restrict__ Wv,
                                               const float* __restrict__ Wo)
{
    __shared__ float t[32][33];
    int z = blockIdx.z;
    const float* W = (z == 0) ? Wv : Wo;
    __half* Bp = (z == 0) ? g_Bvh : g_Boh;
    int n0 = blockIdx.x * 32, k0 = blockIdx.y * 32;
    int tx = threadIdx.x & 31, ty = threadIdx.x >> 5;
#pragma unroll
    for (int i = 0; i < 4; i++)
        t[ty + i * 8][tx] = W[(size_t)(k0 + ty + i * 8) * 512 + n0 + tx];
    __syncthreads();
#pragma unroll
    for (int i = 0; i < 4; i++) {
        int n = n0 + ty + i * 8, k = k0 + tx;
        Bp[(size_t)n * 512 + k] = __float2half(t[tx][ty + i * 8]);
    }
}

// ---------------------------------------------------------------------------
// bf16 3-term dense GEMM (Q/K projections). 4 warps of 64x64, BK=32, 2-stage.
// ---------------------------------------------------------------------------
#define PANEL 10240
#define STAGE 40960

template <int MODE>  // 0: Q proj -> g_Qs ; 1: K proj -> g_Ks
__global__ __launch_bounds__(128) void mma_gemm(const float* __restrict__ bias)
{
    const bf16* A  = (MODE == 0) ? g_Aq : g_Ak;
    const bf16* Bp = (MODE == 0) ? g_Bq : g_Bk;
    extern __shared__ char sm[];
    uint32_t sb = smem_u32(sm);
    const int tid = threadIdx.x, lane = tid & 31, wid = tid >> 5;
    const int wy = wid >> 1, wx = wid & 1;
    const int row0 = blockIdx.y * 128, col0 = blockIdx.x * 128;

    const uint32_t aOff = ((wy * 64 + (lane & 15)) * 40 + ((lane >> 4) << 3)) * 2;
    const uint32_t bOff =
        ((wx * 64 + ((lane >> 4) << 3) + (lane & 7)) * 40 + (lane & 8)) * 2;

    float acc[4][8][4];
#pragma unroll
    for (int i = 0; i < 4; i++)
#pragma unroll
        for (int j = 0; j < 8; j++)
#pragma unroll
            for (int q = 0; q < 4; q++) acc[i][j][q] = 0.f;

#define FILL_D(kk, st)                                                          \
    {                                                                           \
        uint32_t stb = sb + (st)*STAGE;                                         \
        _Pragma("unroll") for (int i = 0; i < 4; i++)                           \
        {                                                                       \
            int s = tid + i * 128;                                              \
            int r = s >> 2, c = s & 3;                                          \
            uint32_t off = (uint32_t)(r * 40 + c * 8) * 2;                      \
            const bf16* a0 = A + (size_t)(row0 + r) * 1024 + (kk)*32 + c * 8;   \
            const bf16* b0 = Bp + (size_t)(col0 + r) * 1024 + (kk)*32 + c * 8;  \
            CP16(stb + off, a0);                                                \
            CP16(stb + PANEL + off, a0 + 512);                                  \
            CP16(stb + 2 * PANEL + off, b0);                                    \
            CP16(stb + 3 * PANEL + off, b0 + 512);                              \
        }                                                                       \
        CP_COMMIT();                                                            \
    }

    FILL_D(0, 0);
    FILL_D(1, 1);
    for (int kk = 0; kk < 16; kk++) {
        if (kk < 15) CP_WAIT(1); else CP_WAIT(0);
        __syncthreads();
        uint32_t stb = sb + (kk & 1) * STAGE;
#pragma unroll
        for (int ks = 0; ks < 2; ks++) {
            uint32_t ah[4][4], al[4][4], bh[4][4], bl[4][4];
#pragma unroll
            for (int mi = 0; mi < 4; mi++) {
                ldsm4(ah[mi], stb + aOff + mi * 1280 + ks * 32);
                ldsm4(al[mi], stb + PANEL + aOff + mi * 1280 + ks * 32);
            }
#pragma unroll
            for (int ng = 0; ng < 4; ng++) {
                ldsm4(bh[ng], stb + 2 * PANEL + bOff + ng * 1280 + ks * 32);
                ldsm4(bl[ng], stb + 3 * PANEL + bOff + ng * 1280 + ks * 32);
            }
#pragma unroll
            for (int mi = 0; mi < 4; mi++)
#pragma unroll
                for (int ni = 0; ni < 8; ni++) {
                    uint32_t bh0 = bh[ni >> 1][(ni & 1) * 2];
                    uint32_t bh1 = bh[ni >> 1][(ni & 1) * 2 + 1];
                    mma_bf16(acc[mi][ni], ah[mi], bh0, bh1);
                    mma_bf16(acc[mi][ni], al[mi], bh0, bh1);
                    mma_bf16(acc[mi][ni], ah[mi],
                             bl[ni >> 1][(ni & 1) * 2],
                             bl[ni >> 1][(ni & 1) * 2 + 1]);
                }
        }
        __syncthreads();
        if (kk + 2 < 16) FILL_D(kk + 2, kk & 1);
    }

#pragma unroll
    for (int mi = 0; mi < 4; mi++)
#pragma unroll
        for (int ni = 0; ni < 8; ni++) {
            int r0 = row0 + wy * 64 + mi * 16 + (lane >> 2);
            int cc = col0 + wx * 64 + ni * 8 + (lane & 3) * 2;
            float b0 = __ldg(&bias[cc]), b1 = __ldg(&bias[cc + 1]);
#pragma unroll
            for (int half = 0; half < 2; half++) {
                int r = r0 + half * 8;
                float v0 = acc[mi][ni][half * 2] + b0;
                float v1 = acc[mi][ni][half * 2 + 1] + b1;
                int bh = ((r >> 9) << 3) + (cc >> 6), l = r & 511, d = cc & 63;
                bf16 h0 = __float2bfloat16(v0), h1 = __float2bfloat16(v1);
                bf16 l0 = __float2bfloat16(v0 - __bfloat162float(h0));
                bf16 l1 = __float2bfloat16(v1 - __bfloat162float(h1));
                bf16* dst =
                    ((MODE == 0) ? g_Qs : g_Ks) + ((size_t)bh * 512 + l) * 128 + d;
                *(__nv_bfloat162*)dst        = __halves2bfloat162(h0, h1);
                *(__nv_bfloat162*)(dst + 64) = __halves2bfloat162(l0, l1);
            }
        }
}

// ---------------------------------------------------------------------------
// fp16 single-term dense GEMM. 4 warps of 64x64, BK=64 (2x k32 panels), 2-stage.
// MODE 0: V proj (A=g_Avh, B=g_Bvh) -> g_Vh fp32 head-split (+bv)
// MODE 1: out    (A=g_Aath, B=g_Boh) -> Y row-major (+bo)
// ---------------------------------------------------------------------------
template <int MODE>
__global__ __launch_bounds__(128) void gemm_h(const float* __restrict__ bias,
                                              float* __restrict__ Y)
{
    const __half* A = (MODE == 0) ? g_Avh : g_Aath;
    const __half* B = (MODE == 0) ? g_Bvh : g_Boh;
    extern __shared__ char sm[];
    uint32_t sb = smem_u32(sm);
    const int tid = threadIdx.x, lane = tid & 31, wid = tid >> 5;
    const int wy = wid >> 1, wx = wid & 1;
    const int row0 = blockIdx.y * 128, col0 = blockIdx.x * 128;

    const uint32_t aOff = ((wy * 64 + (lane & 15)) * 40 + ((lane >> 4) << 3)) * 2;
    const uint32_t bOff =
        ((wx * 64 + ((lane >> 4) << 3) + (lane & 7)) * 40 + (lane & 8)) * 2;

    float acc[4][8][4];
#pragma unroll
    for (int i = 0; i < 4; i++)
#pragma unroll
        for (int j = 0; j < 8; j++)
#pragma unroll
            for (int q = 0; q < 4; q++) acc[i][j][q] = 0.f;

#define FILL_H(kk, st)                                                          \
    {                                                                           \
        uint32_t stb = sb + (st)*STAGE;                                         \
        _Pragma("unroll") for (int i = 0; i < 4; i++)                           \
        {                                                                       \
            int s = tid + i * 128;                                              \
            int r = s >> 2, c = s & 3;                                          \
            uint32_t off = (uint32_t)(r * 40 + c * 8) * 2;                      \
            const __half* a0 = A + (size_t)(row0 + r) * 512 + (kk)*64 + c * 8;  \
            const __half* b0 = B + (size_t)(col0 + r) * 512 + (kk)*64 + c * 8;  \
            CP16(stb + off, a0);                                                \
            CP16(stb + PANEL + off, a0 + 32);                                   \
            CP16(stb + 2 * PANEL + off, b0);                                    \
            CP16(stb + 3 * PANEL + off, b0 + 32);                               \
        }                                                                       \
        CP_COMMIT();                                                            \
    }

    FILL_H(0, 0);
    FILL_H(1, 1);
    for (int kk = 0; kk < 8; kk++) {
        if (kk < 7) CP_WAIT(1); else CP_WAIT(0);
        __syncthreads();
        uint32_t stb = sb + (kk & 1) * STAGE;
#pragma unroll
        for (int sub = 0; sub < 2; sub++) {
            uint32_t ap = stb + sub * PANEL;
            uint32_t bp = stb + (2 + sub) * PANEL;
#pragma unroll
            for (int ks = 0; ks < 2; ks++) {
                uint32_t af[4][4], bfr[4][4];
#pragma unroll
                for (int mi = 0; mi < 4; mi++)
                    ldsm4(af[mi], ap + aOff + mi * 1280 + ks * 32);
#pragma unroll
                for (int ng = 0; ng < 4; ng++)
                    ldsm4(bfr[ng], bp + bOff + ng * 1280 + ks * 32);
#pragma unroll
                for (int mi = 0; mi < 4; mi++)
#pragma unroll
                    for (int ni = 0; ni < 8; ni++)
                        mma_f16(acc[mi][ni], af[mi],
                                bfr[ni >> 1][(ni & 1) * 2],
                                bfr[ni >> 1][(ni & 1) * 2 + 1]);
            }
        }
        __syncthreads();
        if (kk + 2 < 8) FILL_H(kk + 2, kk & 1);
    }

#pragma unroll
    for (int mi = 0; mi < 4; mi++)
#pragma unroll
        for (int ni = 0; ni < 8; ni++) {
            int r0 = row0 + wy * 64 + mi * 16 + (lane >> 2);
            int cc = col0 + wx * 64 + ni * 8 + (lane & 3) * 2;
            float b0 = __ldg(&bias[cc]), b1 = __ldg(&bias[cc + 1]);
#pragma unroll
            for (int half = 0; half < 2; half++) {
                int r = r0 + half * 8;
                float v0 = acc[mi][ni][half * 2] + b0;
                float v1 = acc[mi][ni][half * 2 + 1] + b1;
                if (MODE == 1) {
                    *(float2*)(Y + (size_t)r * 512 + cc) = make_float2(v0, v1);
                } else {
                    int bh = ((r >> 9) << 3) + (cc >> 6), l = r & 511, d = cc & 63;
                    *(float2*)(g_Vh + ((size_t)bh * 512 + l) * 64 + d) =
                        make_float2(v0, v1);
                }
            }
        }
}

// ---------------------------------------------------------------------------
// V transpose: g_Vh [bh][512][64] fp32 -> g_Vth [bh][64][512] fp16
// ---------------------------------------------------------------------------
__global__ __launch_bounds__(256) void vtrans()
{
    int l0 = blockIdx.x * 64, bh = blockIdx.y;
    __shared__ float sm[64][68];
    const float* V = g_Vh + (size_t)bh * 512 * 64;
    int tid = threadIdx.x;
#pragma unroll
    for (int i = 0; i < 4; i++) {
        int idx4 = tid + i * 256;
        int r = idx4 >> 4, c4 = (idx4 & 15) * 4;
        *(float4*)&sm[r][c4] = *(const float4*)(V + (size_t)(l0 + r) * 64 + c4);
    }
    __syncthreads();
    __half* O = g_Vth + (size_t)bh * 64 * 512;
#pragma unroll
    for (int i = 0; i < 16; i++) {
        int e = tid + i * 256;
        int d = e >> 6, l = e & 63;
        O[(size_t)d * 512 + l0 + l] = __float2half(sm[l][d]);
    }
}

// ---------------------------------------------------------------------------
// qk: S = Qs @ Ks^T per bh (bf16 3-term). 4 warps of 64x64; K resident.
// ---------------------------------------------------------------------------
__global__ __launch_bounds__(128) void qk_mma()
{
    int tk = blockIdx.x, tq = blockIdx.y, bh = blockIdx.z;
    if (tk > tq) return;
    const bf16* Aq = g_Qs + (size_t)bh * 512 * 128;
    const bf16* Bk = g_Ks + (size_t)bh * 512 * 128;
    extern __shared__ char sm[];
    uint32_t sb = smem_u32(sm);
    const int tid = threadIdx.x, lane = tid & 31, wid = tid >> 5;
    const int wy = wid >> 1, wx = wid & 1;
    const int row0 = tq * 128, col0 = tk * 128;

    const uint32_t aOff = ((wy * 64 + (lane & 15)) * 40 + ((lane >> 4) << 3)) * 2;
    const uint32_t bOff =
        ((wx * 64 + ((lane >> 4) << 3) + (lane & 7)) * 40 + (lane & 8)) * 2;

#pragma unroll
    for (int p = 0; p < 4; p++) {
        int part = p >> 1, kk = p & 1;
        int colb = part * 64 + kk * 32;
#pragma unroll
        for (int i = 0; i < 4; i++) {
            int s = tid + i * 128;
            int r = s >> 2, c = s & 3;
            uint32_t off = (uint32_t)(r * 40 + c * 8) * 2;
            CP16(sb + p * PANEL + off,
                 Aq + (size_t)(row0 + r) * 128 + colb + c * 8);
            CP16(sb + (4 + p) * PANEL + off,
                 Bk + (size_t)(col0 + r) * 128 + colb + c * 8);
        }
    }
    CP_COMMIT();

    float acc[4][8][4];
#pragma unroll
    for (int i = 0; i < 4; i++)
#pragma unroll
        for (int j = 0; j < 8; j++)
#pragma unroll
            for (int q = 0; q < 4; q++) acc[i][j][q] = 0.f;

    CP_WAIT(0);
    __syncthreads();

#pragma unroll
    for (int kk = 0; kk < 2; kk++) {
        uint32_t qh = sb + kk * PANEL, ql = sb + (2 + kk) * PANEL;
        uint32_t kh = sb + (4 + kk) * PANEL, kl = sb + (6 + kk) * PANEL;
#pragma unroll
        for (int ks = 0; ks < 2; ks++) {
            uint32_t ah[4][4], al[4][4], bh[4][4], bl[4][4];
#pragma unroll
            for (int mi = 0; mi < 4; mi++) {
                ldsm4(ah[mi], qh + aOff + mi * 1280 + ks * 32);
                ldsm4(al[mi], ql + aOff + mi * 1280 + ks * 32);
            }
#pragma unroll
            for (int ng = 0; ng < 4; ng++) {
                ldsm4(bh[ng], kh + bOff + ng * 1280 + ks * 32);
                ldsm4(bl[ng], kl + bOff + ng * 1280 + ks * 32);
            }
#pragma unroll
            for (int mi = 0; mi < 4; mi++)
#pragma unroll
                for (int ni = 0; ni < 8; ni++) {
                    uint32_t bh0 = bh[ni >> 1][(ni & 1) * 2];
                    uint32_t bh1 = bh[ni >> 1][(ni & 1) * 2 + 1];
                    mma_bf16(acc[mi][ni], ah[mi], bh0, bh1);
                    mma_bf16(acc[mi][ni], al[mi], bh0, bh1);
                    mma_bf16(acc[mi][ni], ah[mi],
                             bl[ni >> 1][(ni & 1) * 2],
                             bl[ni >> 1][(ni & 1) * 2 + 1]);
                }
        }
    }

    float* Smat = g_S + (size_t)bh * 512 * 512;
#pragma unroll
    for (int mi = 0; mi < 4; mi++)
#pragma unroll
        for (int ni = 0; ni < 8; ni++) {
            int r = row0 + wy * 64 + mi * 16 + (lane >> 2);
            int cc = col0 + wx * 64 + ni * 8 + (lane & 3) * 2;
            *(float2*)(Smat + (size_t)r * 512 + cc) =
                make_float2(acc[mi][ni][0], acc[mi][ni][1]);
            *(float2*)(Smat + (size_t)(r + 8) * 512 + cc) =
                make_float2(acc[mi][ni][2], acc[mi][ni][3]);
        }
}

// ---------------------------------------------------------------------------
// Per-row cumsum + area softmax + fold; emits G fp16 up to tile bound.
// ---------------------------------------------------------------------------
__global__ __launch_bounds__(128) void area_softmax_kernel()
{
    __shared__ float Cb[4][516];
    __shared__ float Tb[4][516];
    __shared__ float Ub[4][516];
    __shared__ float Vb[4][516];

    int wrp = threadIdx.x >> 5;
    int lane = threadIdx.x & 31;
    int t = blockIdx.x * 4 + wrp;
    int bh = blockIdx.y;
    int bound = ((t >> 7) + 1) << 7;  // av reads j < bound only

    const float* Srow = g_S + ((size_t)bh * L_ + t) * L_;
    __half* Grow = g_Gh + ((size_t)bh * L_ + t) * 512;
    float* C = Cb[wrp];
    float* T = Tb[wrp];
    float* U = Ub[wrp];
    float* V = Vb[wrp];

    if (lane == 0) C[0] = 0.f;
    float carry = 0.f;
    int nchunk = (t + 32) >> 5;
    for (int c0 = 0; c0 < nchunk; c0++) {
        int j = c0 * 32 + lane;
        float s = (j <= t) ? Srow[j] : 0.f;
#pragma unroll
        for (int off = 1; off < 32; off <<= 1) {
            float y = __shfl_up_sync(0xffffffffu, s, off);
            if (lane >= off) s += y;
        }
        s += carry;
        C[1 + j] = s;
        carry = __shfl_sync(0xffffffffu, s, 31);
    }
    __syncwarp();

    float m = -1e30f;
    for (int e = lane; e <= t; e += 32) {
        float ce = C[1 + e];
        m = fmaxf(m, ce - C[e]);
        if (e >= 1) m = fmaxf(m, (ce - C[e - 1]) * 0.5f);
        if (e >= 2) m = fmaxf(m, (ce - C[e - 2]) * (1.f / 3.f));
    }
#pragma unroll
    for (int off = 16; off; off >>= 1) m = fmaxf(m, __shfl_xor_sync(0xffffffffu, m, off));

    for (int e = t + 1 + lane; e < bound + 2; e += 32) {
        T[e] = 0.f; U[e] = 0.f; V[e] = 0.f;
    }

    float sum = 0.f;
    for (int e = lane; e <= t; e += 32) {
        float ce = C[1 + e];
        float p1 = __expf(ce - C[e] - m);
        float p2 = (e >= 1) ? __expf((ce - C[e - 1]) * 0.5f - m) : 0.f;
        float p3 = (e >= 2) ? __expf((ce - C[e - 2]) * (1.f / 3.f) - m) : 0.f;
        T[e] = p1 + p2 + p3;
        U[e] = p2 + p3;
        V[e] = p3;
        sum += p1 + p2 + p3;
    }
#pragma unroll
    for (int off = 16; off; off >>= 1) sum += __shfl_xor_sync(0xffffffffu, sum, off);
    float inv = 1.f / sum;
    __syncwarp();

    for (int j = lane; j < bound; j += 32) {
        float g = (j <= t) ? (T[j] + U[j + 1] + V[j + 2]) * inv : 0.f;
        Grow[j] = __float2half(g);
    }
}

// ---------------------------------------------------------------------------
// av: attn = G @ Vt^T per bh, fp16 single-term. 128(M)x64(N), 4 warps, tri skip.
// ---------------------------------------------------------------------------
__global__ __launch_bounds__(128) void av_h()
{
    int tm = blockIdx.x, bh = blockIdx.y;
    const __half* A = g_Gh + (size_t)bh * 512 * 512;
    const __half* Bp = g_Vth + (size_t)bh * 64 * 512;
    __shared__ __half sA[2][128 * 40];
    __shared__ __half sB[2][64 * 40];
    const int tid = threadIdx.x, lane = tid & 31, wy = tid >> 5;
    const int row0 = tm * 128;
    const int rA = tid >> 2, cA = (tid & 3) * 8;

    uint32_t sAu = smem_u32(sA), sBu = smem_u32(sB);
    uint32_t aBase = sAu + (((wy * 32 + (lane & 15)) * 40 + ((lane >> 4) << 3)) << 1);
    uint32_t bBase = sBu + (((((lane >> 4) << 3) + (lane & 7)) * 40 + (lane & 8)) << 1);

    float acc[2][8][4];
#pragma unroll
    for (int i = 0; i < 2; i++)
#pragma unroll
        for (int j = 0; j < 8; j++)
#pragma unroll
            for (int q = 0; q < 4; q++) acc[i][j][q] = 0.f;

    uint4 pa[4], pb[2];
#define LDT_H(jc)                                                                   \
    {                                                                               \
        _Pragma("unroll") for (int i = 0; i < 4; i++)                               \
            pa[i] = *(const uint4*)(A + (size_t)(row0 + rA + i * 32) * 512 +        \
                                    (jc)*32 + cA);                                  \
        _Pragma("unroll") for (int i = 0; i < 2; i++)                               \
            pb[i] = *(const uint4*)(Bp + (size_t)(rA + i * 32) * 512 + (jc)*32 + cA); \
    }
#define STT_H(b)                                                                    \
    {                                                                               \
        _Pragma("unroll") for (int i = 0; i < 4; i++)                               \
            *(uint4*)&sA[b][(rA + i * 32) * 40 + cA] = pa[i];                       \
        _Pragma("unroll") for (int i = 0; i < 2; i++)                               \
            *(uint4*)&sB[b][(rA + i * 32) * 40 + cA] = pb[i];                       \
    }

    int nj = (tm + 1) * 4;
    LDT_H(0); STT_H(0); __syncthreads();
    for (int it = 0; it < nj; it++) {
        int b = it & 1;
        if (it < nj - 1) LDT_H(it + 1);
        uint32_t af[2][2][4], bfr[4][2][4];
        uint32_t aB = aBase + b * 10240, bB = bBase + b * 5120;
#pragma unroll
        for (int mi = 0; mi < 2; mi++)
#pragma unroll
            for (int ks = 0; ks < 2; ks++) ldsm4(af[mi][ks], aB + mi * 1280 + ks * 32);
#pragma unroll
        for (int ng = 0; ng < 4; ng++)
#pragma unroll
            for (int ks = 0; ks < 2; ks++) ldsm4(bfr[ng][ks], bB + ng * 1280 + ks * 32);
#pragma unroll
        for (int ks = 0; ks < 2; ks++)
#pragma unroll
            for (int mi = 0; mi < 2; mi++)
#pragma unroll
                for (int ni = 0; ni < 8; ni++)
                    mma_f16(acc[mi][ni], af[mi][ks],
                            bfr[ni >> 1][ks][(ni & 1) * 2],
                            bfr[ni >> 1][ks][(ni & 1) * 2 + 1]);
        if (it < nj - 1) { STT_H(b ^ 1); __syncthreads(); }
    }

    int b_ = bh >> 3, h_ = bh & 7;
#pragma unroll
    for (int mi = 0; mi < 2; mi++)
#pragma unroll
        for (int ni = 0; ni < 8; ni++) {
            int t0 = row0 + wy * 32 + mi * 16 + (lane >> 2);
            int d = ni * 8 + (lane & 3) * 2;
#pragma unroll
            for (int half = 0; half < 2; half++) {
                int t = t0 + half * 8;
                __half2 hv = __floats2half2_rn(acc[mi][ni][half * 2],
                                               acc[mi][ni][half * 2 + 1]);
                *(__half2*)(g_Aath + ((size_t)(b_ * 512 + t)) * 512 + h_ * 64 + d) = hv;
            }
        }
}

// ---------------------------------------------------------------------------
extern "C" void kernel_launch(void* const* d_in, const int* in_sizes, int n_in,
                              void* d_out, int out_size)
{
    const float* q  = (const float*)d_in[0];
    const float* k  = (const float*)d_in[1];
    const float* v  = (const float*)d_in[2];
    // d_in[3] = attn_mask — analytic (area end <= t), unused.
    const float* Wq = (const float*)d_in[4];
    const float* bq = (const float*)d_in[5];
    const float* Wk = (const float*)d_in[6];
    const float* bk = (const float*)d_in[7];
    const float* Wv = (const float*)d_in[8];
    const float* bv = (const float*)d_in[9];
    const float* Wo = (const float*)d_in[10];
    const float* bo = (const float*)d_in[11];
    float* out = (float*)d_out;

    cudaFuncSetAttribute(mma_gemm<0>, cudaFuncAttributeMaxDynamicSharedMemorySize, 81920);
    cudaFuncSetAttribute(mma_gemm<1>, cudaFuncAttributeMaxDynamicSharedMemorySize, 81920);
    cudaFuncSetAttribute(gemm_h<0>, cudaFuncAttributeMaxDynamicSharedMemorySize, 81920);
    cudaFuncSetAttribute(gemm_h<1>, cudaFuncAttributeMaxDynamicSharedMemorySize, 81920);
    cudaFuncSetAttribute(qk_mma, cudaFuncAttributeMaxDynamicSharedMemorySize, 81920);

    convW_all<<<dim3(16, 16, 2), 256>>>(Wq, Wk);
    convW_h<<<dim3(16, 16, 2), 256>>>(Wv, Wo);
    convX_all<<<dim3(4096, 1, 2), 256>>>(q, k);
    convV_h<<<4096, 256>>>(v);

    dim3 gG(4, 64);
    mma_gemm<0><<<gG, 128, 81920>>>(bq);
    mma_gemm<1><<<gG, 128, 81920>>>(bk);
    gemm_h<0><<<gG, 128, 81920>>>(bv, nullptr);

    vtrans<<<dim3(8, 128), 256>>>();
    qk_mma<<<dim3(4, 4, 128), 128, 81920>>>();
    area_softmax_kernel<<<dim3(128, 128), 128>>>();
    av_h<<<dim3(4, 128), 128>>>();

    gemm_h<1><<<gG, 128, 81920>>>(bo, out);
}

// round 9
// speedup vs baseline: 3.0579x; 1.0001x over previous
#include <cuda_runtime.h>
#include <cuda_bf16.h>
#include <cuda_fp16.h>
#include <cstdint>

// ---------------------------------------------------------------------------
// MultiHeadAreaAttention. Precision-tiered tensor-core pipeline:
//   Q/K chain (proj Q, proj K, QK^T): split-bf16 3-term (needs ~1e-4 logits)
//   V path (proj V, G@V, out proj):   single-term fp16 (tolerates ~1e-4 rel)
// ---------------------------------------------------------------------------

#define BH_ 128
#define L_  512
typedef __nv_bfloat16 bf16;

// bf16 split operands for Q/K chain
__device__ bf16 g_Aq[(size_t)8192 * 1024];
__device__ bf16 g_Ak[(size_t)8192 * 1024];
__device__ bf16 g_Bq[512 * 1024];
__device__ bf16 g_Bk[512 * 1024];
__device__ bf16 g_Qs[(size_t)BH_ * 512 * 128];  // [bh][l][hi64|lo64]
__device__ bf16 g_Ks[(size_t)BH_ * 512 * 128];

// fp16 single operands for V path
__device__ __half g_Avh[(size_t)8192 * 512];     // fp16(v)
__device__ __half g_Bvh[512 * 512];              // fp16(Wv)^T  (n-major)
__device__ __half g_Boh[512 * 512];              // fp16(Wo)^T
__device__ __half g_Vth[(size_t)BH_ * 64 * 512]; // V^T per bh
__device__ __half g_Gh[(size_t)BH_ * 512 * 512]; // softmax-folded G
__device__ __half g_Aath[(size_t)8192 * 512];    // attn rows [b*512+t][h*64+d]

__device__ float g_Vh[(size_t)BH_ * 512 * 64];   // fp32 V heads (proj V out)
__device__ float g_S[(size_t)BH_ * 512 * 512];   // scores fp32

// ---------------------------------------------------------------------------
static __device__ __forceinline__ uint32_t smem_u32(const void* p) {
    uint32_t a;
    asm("{ .reg .u64 t; cvta.to.shared.u64 t, %1; cvt.u32.u64 %0, t; }"
        : "=r"(a) : "l"(p));
    return a;
}
static __device__ __forceinline__ void ldsm4(uint32_t* r, uint32_t a) {
    asm volatile("ldmatrix.sync.aligned.m8n8.x4.shared.b16 {%0,%1,%2,%3}, [%4];"
                 : "=r"(r[0]), "=r"(r[1]), "=r"(r[2]), "=r"(r[3]) : "r"(a));
}
static __device__ __forceinline__ void mma_bf16(float* d, const uint32_t* a,
                                                uint32_t b0, uint32_t b1) {
    asm volatile(
        "mma.sync.aligned.m16n8k16.row.col.f32.bf16.bf16.f32 "
        "{%0,%1,%2,%3},{%4,%5,%6,%7},{%8,%9},{%0,%1,%2,%3};"
        : "+f"(d[0]), "+f"(d[1]), "+f"(d[2]), "+f"(d[3])
        : "r"(a[0]), "r"(a[1]), "r"(a[2]), "r"(a[3]), "r"(b0), "r"(b1));
}
static __device__ __forceinline__ void mma_f16(float* d, const uint32_t* a,
                                               uint32_t b0, uint32_t b1) {
    asm volatile(
        "mma.sync.aligned.m16n8k16.row.col.f32.f16.f16.f32 "
        "{%0,%1,%2,%3},{%4,%5,%6,%7},{%8,%9},{%0,%1,%2,%3};"
        : "+f"(d[0]), "+f"(d[1]), "+f"(d[2]), "+f"(d[3])
        : "r"(a[0]), "r"(a[1]), "r"(a[2]), "r"(a[3]), "r"(b0), "r"(b1));
}
#define CP16(dst, src)                                                         \
    asm volatile("cp.async.cg.shared.global [%0], [%1], 16;" ::"r"(dst),       \
                 "l"(src))
#define CP_COMMIT() asm volatile("cp.async.commit_group;")
#define CP_WAIT(n) asm volatile("cp.async.wait_group %0;" ::"n"(n))

// ---------------------------------------------------------------------------
// conversions
// ---------------------------------------------------------------------------
__global__ __launch_bounds__(256) void convX_all(const float* __restrict__ q,
                                                 const float* __restrict__ k)
{
    int z = blockIdx.z;
    const float* X = (z == 0) ? q : k;
    bf16* A = (z == 0) ? g_Aq : g_Ak;
    size_t i4 = (size_t)blockIdx.x * 256 + threadIdx.x;
    size_t r = i4 >> 7;
    int kq = (int)(i4 & 127) * 4;
    float4 x = *(const float4*)(X + r * 512 + kq);
    bf16 h0 = __float2bfloat16(x.x), h1 = __float2bfloat16(x.y);
    bf16 h2 = __float2bfloat16(x.z), h3 = __float2bfloat16(x.w);
    bf16 l0 = __float2bfloat16(x.x - __bfloat162float(h0));
    bf16 l1 = __float2bfloat16(x.y - __bfloat162float(h1));
    bf16 l2 = __float2bfloat16(x.z - __bfloat162float(h2));
    bf16 l3 = __float2bfloat16(x.w - __bfloat162float(h3));
    __nv_bfloat162* p0 = (__nv_bfloat162*)(A + r * 1024 + kq);
    __nv_bfloat162* p1 = (__nv_bfloat162*)(A + r * 1024 + 512 + kq);
    p0[0] = __halves2bfloat162(h0, h1);
    p0[1] = __halves2bfloat162(h2, h3);
    p1[0] = __halves2bfloat162(l0, l1);
    p1[1] = __halves2bfloat162(l2, l3);
}

__global__ __launch_bounds__(256) void convV_h(const float* __restrict__ v)
{
    size_t idx = (size_t)blockIdx.x * 256 + threadIdx.x;  // 1M float4 groups
    float4 x = ((const float4*)v)[idx];
    __half2* p = (__half2*)(g_Avh + idx * 4);
    p[0] = __floats2half2_rn(x.x, x.y);
    p[1] = __floats2half2_rn(x.z, x.w);
}

__global__ __launch_bounds__(256) void convW_all(const float* __restrict__ Wq,
                                                 const float* __restrict__ Wk)
{
    __shared__ float t[32][33];
    int z = blockIdx.z;
    const float* W = (z == 0) ? Wq : Wk;
    bf16* Bp = (z == 0) ? g_Bq : g_Bk;
    int n0 = blockIdx.x * 32, k0 = blockIdx.y * 32;
    int tx = threadIdx.x & 31, ty = threadIdx.x >> 5;
#pragma unroll
    for (int i = 0; i < 4; i++)
        t[ty + i * 8][tx] = W[(size_t)(k0 + ty + i * 8) * 512 + n0 + tx];
    __syncthreads();
#pragma unroll
    for (int i = 0; i < 4; i++) {
        int n = n0 + ty + i * 8, k = k0 + tx;
        float w = t[tx][ty + i * 8];
        bf16 h = __float2bfloat16(w);
        bf16 l = __float2bfloat16(w - __bfloat162float(h));
        Bp[(size_t)n * 1024 + k]       = h;
        Bp[(size_t)n * 1024 + 512 + k] = l;
    }
}

__global__ __launch_bounds__(256) void convW_h(const float* __restrict__ Wv,
                                               const float* __restrict__ Wo)
{
    __shared__ float t[32][33];
    int z = blockIdx.z;
    const float* W = (z == 0) ? Wv : Wo;
    __half* Bp = (z == 0) ? g_Bvh : g_Boh;
    int n0 = blockIdx.x * 32, k0 = blockIdx.y * 32;
    int tx = threadIdx.x & 31, ty = threadIdx.x >> 5;
#pragma unroll
    for (int i = 0; i < 4; i++)
        t[ty + i * 8][tx] = W[(size_t)(k0 + ty + i * 8) * 512 + n0 + tx];
    __syncthreads();
#pragma unroll
    for (int i = 0; i < 4; i++) {
        int n = n0 + ty + i * 8, k = k0 + tx;
        Bp[(size_t)n * 512 + k] = __float2half(t[tx][ty + i * 8]);
    }
}

// ---------------------------------------------------------------------------
// bf16 3-term dense GEMM (Q/K projections). 4 warps of 64x64, BK=32, 2-stage.
// ---------------------------------------------------------------------------
#define PANEL 10240
#define STAGE 40960

template <int MODE>  // 0: Q proj -> g_Qs ; 1: K proj -> g_Ks
__global__ __launch_bounds__(128) void mma_gemm(const float* __restrict__ bias)
{
    const bf16* A  = (MODE == 0) ? g_Aq : g_Ak;
    const bf16* Bp = (MODE == 0) ? g_Bq : g_Bk;
    extern __shared__ char sm[];
    uint32_t sb = smem_u32(sm);
    const int tid = threadIdx.x, lane = tid & 31, wid = tid >> 5;
    const int wy = wid >> 1, wx = wid & 1;
    const int row0 = blockIdx.y * 128, col0 = blockIdx.x * 128;

    const uint32_t aOff = ((wy * 64 + (lane & 15)) * 40 + ((lane >> 4) << 3)) * 2;
    const uint32_t bOff =
        ((wx * 64 + ((lane >> 4) << 3) + (lane & 7)) * 40 + (lane & 8)) * 2;

    float acc[4][8][4];
#pragma unroll
    for (int i = 0; i < 4; i++)
#pragma unroll
        for (int j = 0; j < 8; j++)
#pragma unroll
            for (int q = 0; q < 4; q++) acc[i][j][q] = 0.f;

#define FILL_D(kk, st)                                                          \
    {                                                                           \
        uint32_t stb = sb + (st)*STAGE;                                         \
        _Pragma("unroll") for (int i = 0; i < 4; i++)                           \
        {                                                                       \
            int s = tid + i * 128;                                              \
            int r = s >> 2, c = s & 3;                                          \
            uint32_t off = (uint32_t)(r * 40 + c * 8) * 2;                      \
            const bf16* a0 = A + (size_t)(row0 + r) * 1024 + (kk)*32 + c * 8;   \
            const bf16* b0 = Bp + (size_t)(col0 + r) * 1024 + (kk)*32 + c * 8;  \
            CP16(stb + off, a0);                                                \
            CP16(stb + PANEL + off, a0 + 512);                                  \
            CP16(stb + 2 * PANEL + off, b0);                                    \
            CP16(stb + 3 * PANEL + off, b0 + 512);                              \
        }                                                                       \
        CP_COMMIT();                                                            \
    }

    FILL_D(0, 0);
    FILL_D(1, 1);
    for (int kk = 0; kk < 16; kk++) {
        if (kk < 15) CP_WAIT(1); else CP_WAIT(0);
        __syncthreads();
        uint32_t stb = sb + (kk & 1) * STAGE;
#pragma unroll
        for (int ks = 0; ks < 2; ks++) {
            uint32_t ah[4][4], al[4][4], bh[4][4], bl[4][4];
#pragma unroll
            for (int mi = 0; mi < 4; mi++) {
                ldsm4(ah[mi], stb + aOff + mi * 1280 + ks * 32);
                ldsm4(al[mi], stb + PANEL + aOff + mi * 1280 + ks * 32);
            }
#pragma unroll
            for (int ng = 0; ng < 4; ng++) {
                ldsm4(bh[ng], stb + 2 * PANEL + bOff + ng * 1280 + ks * 32);
                ldsm4(bl[ng], stb + 3 * PANEL + bOff + ng * 1280 + ks * 32);
            }
#pragma unroll
            for (int mi = 0; mi < 4; mi++)
#pragma unroll
                for (int ni = 0; ni < 8; ni++) {
                    uint32_t bh0 = bh[ni >> 1][(ni & 1) * 2];
                    uint32_t bh1 = bh[ni >> 1][(ni & 1) * 2 + 1];
                    mma_bf16(acc[mi][ni], ah[mi], bh0, bh1);
                    mma_bf16(acc[mi][ni], al[mi], bh0, bh1);
                    mma_bf16(acc[mi][ni], ah[mi],
                             bl[ni >> 1][(ni & 1) * 2],
                             bl[ni >> 1][(ni & 1) * 2 + 1]);
                }
        }
        __syncthreads();
        if (kk + 2 < 16) FILL_D(kk + 2, kk & 1);
    }

#pragma unroll
    for (int mi = 0; mi < 4; mi++)
#pragma unroll
        for (int ni = 0; ni < 8; ni++) {
            int r0 = row0 + wy * 64 + mi * 16 + (lane >> 2);
            int cc = col0 + wx * 64 + ni * 8 + (lane & 3) * 2;
            float b0 = __ldg(&bias[cc]), b1 = __ldg(&bias[cc + 1]);
#pragma unroll
            for (int half = 0; half < 2; half++) {
                int r = r0 + half * 8;
                float v0 = acc[mi][ni][half * 2] + b0;
                float v1 = acc[mi][ni][half * 2 + 1] + b1;
                int bh = ((r >> 9) << 3) + (cc >> 6), l = r & 511, d = cc & 63;
                bf16 h0 = __float2bfloat16(v0), h1 = __float2bfloat16(v1);
                bf16 l0 = __float2bfloat16(v0 - __bfloat162float(h0));
                bf16 l1 = __float2bfloat16(v1 - __bfloat162float(h1));
                bf16* dst =
                    ((MODE == 0) ? g_Qs : g_Ks) + ((size_t)bh * 512 + l) * 128 + d;
                *(__nv_bfloat162*)dst        = __halves2bfloat162(h0, h1);
                *(__nv_bfloat162*)(dst + 64) = __halves2bfloat162(l0, l1);
            }
        }
}

// ---------------------------------------------------------------------------
// fp16 single-term dense GEMM. 4 warps of 64x64, BK=64 (2x k32 panels), 2-stage.
// MODE 0: V proj (A=g_Avh, B=g_Bvh) -> g_Vh fp32 head-split (+bv)
// MODE 1: out    (A=g_Aath, B=g_Boh) -> Y row-major (+bo)
// ---------------------------------------------------------------------------
template <int MODE>
__global__ __launch_bounds__(128) void gemm_h(const float* __restrict__ bias,
                                              float* __restrict__ Y)
{
    const __half* A = (MODE == 0) ? g_Avh : g_Aath;
    const __half* B = (MODE == 0) ? g_Bvh : g_Boh;
    extern __shared__ char sm[];
    uint32_t sb = smem_u32(sm);
    const int tid = threadIdx.x, lane = tid & 31, wid = tid >> 5;
    const int wy = wid >> 1, wx = wid & 1;
    const int row0 = blockIdx.y * 128, col0 = blockIdx.x * 128;

    const uint32_t aOff = ((wy * 64 + (lane & 15)) * 40 + ((lane >> 4) << 3)) * 2;
    const uint32_t bOff =
        ((wx * 64 + ((lane >> 4) << 3) + (lane & 7)) * 40 + (lane & 8)) * 2;

    float acc[4][8][4];
#pragma unroll
    for (int i = 0; i < 4; i++)
#pragma unroll
        for (int j = 0; j < 8; j++)
#pragma unroll
            for (int q = 0; q < 4; q++) acc[i][j][q] = 0.f;

#define FILL_H(kk, st)                                                          \
    {                                                                           \
        uint32_t stb = sb + (st)*STAGE;                                         \
        _Pragma("unroll") for (int i = 0; i < 4; i++)                           \
        {                                                                       \
            int s = tid + i * 128;                                              \
            int r = s >> 2, c = s & 3;                                          \
            uint32_t off = (uint32_t)(r * 40 + c * 8) * 2;                      \
            const __half* a0 = A + (size_t)(row0 + r) * 512 + (kk)*64 + c * 8;  \
            const __half* b0 = B + (size_t)(col0 + r) * 512 + (kk)*64 + c * 8;  \
            CP16(stb + off, a0);                                                \
            CP16(stb + PANEL + off, a0 + 32);                                   \
            CP16(stb + 2 * PANEL + off, b0);                                    \
            CP16(stb + 3 * PANEL + off, b0 + 32);                               \
        }                                                                       \
        CP_COMMIT();                                                            \
    }

    FILL_H(0, 0);
    FILL_H(1, 1);
    for (int kk = 0; kk < 8; kk++) {
        if (kk < 7) CP_WAIT(1); else CP_WAIT(0);
        __syncthreads();
        uint32_t stb = sb + (kk & 1) * STAGE;
#pragma unroll
        for (int sub = 0; sub < 2; sub++) {
            uint32_t ap = stb + sub * PANEL;
            uint32_t bp = stb + (2 + sub) * PANEL;
#pragma unroll
            for (int ks = 0; ks < 2; ks++) {
                uint32_t af[4][4], bfr[4][4];
#pragma unroll
                for (int mi = 0; mi < 4; mi++)
                    ldsm4(af[mi], ap + aOff + mi * 1280 + ks * 32);
#pragma unroll
                for (int ng = 0; ng < 4; ng++)
                    ldsm4(bfr[ng], bp + bOff + ng * 1280 + ks * 32);
#pragma unroll
                for (int mi = 0; mi < 4; mi++)
#pragma unroll
                    for (int ni = 0; ni < 8; ni++)
                        mma_f16(acc[mi][ni], af[mi],
                                bfr[ni >> 1][(ni & 1) * 2],
                                bfr[ni >> 1][(ni & 1) * 2 + 1]);
            }
        }
        __syncthreads();
        if (kk + 2 < 8) FILL_H(kk + 2, kk & 1);
    }

#pragma unroll
    for (int mi = 0; mi < 4; mi++)
#pragma unroll
        for (int ni = 0; ni < 8; ni++) {
            int r0 = row0 + wy * 64 + mi * 16 + (lane >> 2);
            int cc = col0 + wx * 64 + ni * 8 + (lane & 3) * 2;
            float b0 = __ldg(&bias[cc]), b1 = __ldg(&bias[cc + 1]);
#pragma unroll
            for (int half = 0; half < 2; half++) {
                int r = r0 + half * 8;
                float v0 = acc[mi][ni][half * 2] + b0;
                float v1 = acc[mi][ni][half * 2 + 1] + b1;
                if (MODE == 1) {
                    *(float2*)(Y + (size_t)r * 512 + cc) = make_float2(v0, v1);
                } else {
                    int bh = ((r >> 9) << 3) + (cc >> 6), l = r & 511, d = cc & 63;
                    *(float2*)(g_Vh + ((size_t)bh * 512 + l) * 64 + d) =
                        make_float2(v0, v1);
                }
            }
        }
}

// ---------------------------------------------------------------------------
// V transpose: g_Vh [bh][512][64] fp32 -> g_Vth [bh][64][512] fp16
// ---------------------------------------------------------------------------
__global__ __launch_bounds__(256) void vtrans()
{
    int l0 = blockIdx.x * 64, bh = blockIdx.y;
    __shared__ float sm[64][68];
    const float* V = g_Vh + (size_t)bh * 512 * 64;
    int tid = threadIdx.x;
#pragma unroll
    for (int i = 0; i < 4; i++) {
        int idx4 = tid + i * 256;
        int r = idx4 >> 4, c4 = (idx4 & 15) * 4;
        *(float4*)&sm[r][c4] = *(const float4*)(V + (size_t)(l0 + r) * 64 + c4);
    }
    __syncthreads();
    __half* O = g_Vth + (size_t)bh * 64 * 512;
#pragma unroll
    for (int i = 0; i < 16; i++) {
        int e = tid + i * 256;
        int d = e >> 6, l = e & 63;
        O[(size_t)d * 512 + l0 + l] = __float2half(sm[l][d]);
    }
}

// ---------------------------------------------------------------------------
// qk: S = Qs @ Ks^T per bh (bf16 3-term). 4 warps of 64x64; K resident.
// ---------------------------------------------------------------------------
__global__ __launch_bounds__(128) void qk_mma()
{
    int tk = blockIdx.x, tq = blockIdx.y, bh = blockIdx.z;
    if (tk > tq) return;
    const bf16* Aq = g_Qs + (size_t)bh * 512 * 128;
    const bf16* Bk = g_Ks + (size_t)bh * 512 * 128;
    extern __shared__ char sm[];
    uint32_t sb = smem_u32(sm);
    const int tid = threadIdx.x, lane = tid & 31, wid = tid >> 5;
    const int wy = wid >> 1, wx = wid & 1;
    const int row0 = tq * 128, col0 = tk * 128;

    const uint32_t aOff = ((wy * 64 + (lane & 15)) * 40 + ((lane >> 4) << 3)) * 2;
    const uint32_t bOff =
        ((wx * 64 + ((lane >> 4) << 3) + (lane & 7)) * 40 + (lane & 8)) * 2;

#pragma unroll
    for (int p = 0; p < 4; p++) {
        int part = p >> 1, kk = p & 1;
        int colb = part * 64 + kk * 32;
#pragma unroll
        for (int i = 0; i < 4; i++) {
            int s = tid + i * 128;
            int r = s >> 2, c = s & 3;
            uint32_t off = (uint32_t)(r * 40 + c * 8) * 2;
            CP16(sb + p * PANEL + off,
                 Aq + (size_t)(row0 + r) * 128 + colb + c * 8);
            CP16(sb + (4 + p) * PANEL + off,
                 Bk + (size_t)(col0 + r) * 128 + colb + c * 8);
        }
    }
    CP_COMMIT();

    float acc[4][8][4];
#pragma unroll
    for (int i = 0; i < 4; i++)
#pragma unroll
        for (int j = 0; j < 8; j++)
#pragma unroll
            for (int q = 0; q < 4; q++) acc[i][j][q] = 0.f;

    CP_WAIT(0);
    __syncthreads();

#pragma unroll
    for (int kk = 0; kk < 2; kk++) {
        uint32_t qh = sb + kk * PANEL, ql = sb + (2 + kk) * PANEL;
        uint32_t kh = sb + (4 + kk) * PANEL, kl = sb + (6 + kk) * PANEL;
#pragma unroll
        for (int ks = 0; ks < 2; ks++) {
            uint32_t ah[4][4], al[4][4], bh[4][4], bl[4][4];
#pragma unroll
            for (int mi = 0; mi < 4; mi++) {
                ldsm4(ah[mi], qh + aOff + mi * 1280 + ks * 32);
                ldsm4(al[mi], ql + aOff + mi * 1280 + ks * 32);
            }
#pragma unroll
            for (int ng = 0; ng < 4; ng++) {
                ldsm4(bh[ng], kh + bOff + ng * 1280 + ks * 32);
                ldsm4(bl[ng], kl + bOff + ng * 1280 + ks * 32);
            }
#pragma unroll
            for (int mi = 0; mi < 4; mi++)
#pragma unroll
                for (int ni = 0; ni < 8; ni++) {
                    uint32_t bh0 = bh[ni >> 1][(ni & 1) * 2];
                    uint32_t bh1 = bh[ni >> 1][(ni & 1) * 2 + 1];
                    mma_bf16(acc[mi][ni], ah[mi], bh0, bh1);
                    mma_bf16(acc[mi][ni], al[mi], bh0, bh1);
                    mma_bf16(acc[mi][ni], ah[mi],
                             bl[ni >> 1][(ni & 1) * 2],
                             bl[ni >> 1][(ni & 1) * 2 + 1]);
                }
        }
    }

    float* Smat = g_S + (size_t)bh * 512 * 512;
#pragma unroll
    for (int mi = 0; mi < 4; mi++)
#pragma unroll
        for (int ni = 0; ni < 8; ni++) {
            int r = row0 + wy * 64 + mi * 16 + (lane >> 2);
            int cc = col0 + wx * 64 + ni * 8 + (lane & 3) * 2;
            *(float2*)(Smat + (size_t)r * 512 + cc) =
                make_float2(acc[mi][ni][0], acc[mi][ni][1]);
            *(float2*)(Smat + (size_t)(r + 8) * 512 + cc) =
                make_float2(acc[mi][ni][2], acc[mi][ni][3]);
        }
}

// ---------------------------------------------------------------------------
// Per-row cumsum + area softmax + fold; emits G fp16 up to tile bound.
// ---------------------------------------------------------------------------
__global__ __launch_bounds__(128) void area_softmax_kernel()
{
    __shared__ float Cb[4][516];
    __shared__ float Tb[4][516];
    __shared__ float Ub[4][516];
    __shared__ float Vb[4][516];

    int wrp = threadIdx.x >> 5;
    int lane = threadIdx.x & 31;
    int t = blockIdx.x * 4 + wrp;
    int bh = blockIdx.y;
    int bound = ((t >> 7) + 1) << 7;  // av reads j < bound only

    const float* Srow = g_S + ((size_t)bh * L_ + t) * L_;
    __half* Grow = g_Gh + ((size_t)bh * L_ + t) * 512;
    float* C = Cb[wrp];
    float* T = Tb[wrp];
    float* U = Ub[wrp];
    float* V = Vb[wrp];

    if (lane == 0) C[0] = 0.f;
    float carry = 0.f;
    int nchunk = (t + 32) >> 5;
    for (int c0 = 0; c0 < nchunk; c0++) {
        int j = c0 * 32 + lane;
        float s = (j <= t) ? Srow[j] : 0.f;
#pragma unroll
        for (int off = 1; off < 32; off <<= 1) {
            float y = __shfl_up_sync(0xffffffffu, s, off);
            if (lane >= off) s += y;
        }
        s += carry;
        C[1 + j] = s;
        carry = __shfl_sync(0xffffffffu, s, 31);
    }
    __syncwarp();

    float m = -1e30f;
    for (int e = lane; e <= t; e += 32) {
        float ce = C[1 + e];
        m = fmaxf(m, ce - C[e]);
        if (e >= 1) m = fmaxf(m, (ce - C[e - 1]) * 0.5f);
        if (e >= 2) m = fmaxf(m, (ce - C[e - 2]) * (1.f / 3.f));
    }
#pragma unroll
    for (int off = 16; off; off >>= 1) m = fmaxf(m, __shfl_xor_sync(0xffffffffu, m, off));

    for (int e = t + 1 + lane; e < bound + 2; e += 32) {
        T[e] = 0.f; U[e] = 0.f; V[e] = 0.f;
    }

    float sum = 0.f;
    for (int e = lane; e <= t; e += 32) {
        float ce = C[1 + e];
        float p1 = __expf(ce - C[e] - m);
        float p2 = (e >= 1) ? __expf((ce - C[e - 1]) * 0.5f - m) : 0.f;
        float p3 = (e >= 2) ? __expf((ce - C[e - 2]) * (1.f / 3.f) - m) : 0.f;
        T[e] = p1 + p2 + p3;
        U[e] = p2 + p3;
        V[e] = p3;
        sum += p1 + p2 + p3;
    }
#pragma unroll
    for (int off = 16; off; off >>= 1) sum += __shfl_xor_sync(0xffffffffu, sum, off);
    float inv = 1.f / sum;
    __syncwarp();

    for (int j = lane; j < bound; j += 32) {
        float g = (j <= t) ? (T[j] + U[j + 1] + V[j + 2]) * inv : 0.f;
        Grow[j] = __float2half(g);
    }
}

// ---------------------------------------------------------------------------
// av: attn = G @ Vt^T per bh, fp16 single-term. 128(M)x64(N), 4 warps, tri skip.
// ---------------------------------------------------------------------------
__global__ __launch_bounds__(128) void av_h()
{
    int tm = blockIdx.x, bh = blockIdx.y;
    const __half* A = g_Gh + (size_t)bh * 512 * 512;
    const __half* Bp = g_Vth + (size_t)bh * 64 * 512;
    __shared__ __half sA[2][128 * 40];
    __shared__ __half sB[2][64 * 40];
    const int tid = threadIdx.x, lane = tid & 31, wy = tid >> 5;
    const int row0 = tm * 128;
    const int rA = tid >> 2, cA = (tid & 3) * 8;

    uint32_t sAu = smem_u32(sA), sBu = smem_u32(sB);
    uint32_t aBase = sAu + (((wy * 32 + (lane & 15)) * 40 + ((lane >> 4) << 3)) << 1);
    uint32_t bBase = sBu + (((((lane >> 4) << 3) + (lane & 7)) * 40 + (lane & 8)) << 1);

    float acc[2][8][4];
#pragma unroll
    for (int i = 0; i < 2; i++)
#pragma unroll
        for (int j = 0; j < 8; j++)
#pragma unroll
            for (int q = 0; q < 4; q++) acc[i][j][q] = 0.f;

    uint4 pa[4], pb[2];
#define LDT_H(jc)                                                                   \
    {                                                                               \
        _Pragma("unroll") for (int i = 0; i < 4; i++)                               \
            pa[i] = *(const uint4*)(A + (size_t)(row0 + rA + i * 32) * 512 +        \
                                    (jc)*32 + cA);                                  \
        _Pragma("unroll") for (int i = 0; i < 2; i++)                               \
            pb[i] = *(const uint4*)(Bp + (size_t)(rA + i * 32) * 512 + (jc)*32 + cA); \
    }
#define STT_H(b)                                                                    \
    {                                                                               \
        _Pragma("unroll") for (int i = 0; i < 4; i++)                               \
            *(uint4*)&sA[b][(rA + i * 32) * 40 + cA] = pa[i];                       \
        _Pragma("unroll") for (int i = 0; i < 2; i++)                               \
            *(uint4*)&sB[b][(rA + i * 32) * 40 + cA] = pb[i];                       \
    }

    int nj = (tm + 1) * 4;
    LDT_H(0); STT_H(0); __syncthreads();
    for (int it = 0; it < nj; it++) {
        int b = it & 1;
        if (it < nj - 1) LDT_H(it + 1);
        uint32_t af[2][2][4], bfr[4][2][4];
        uint32_t aB = aBase + b * 10240, bB = bBase + b * 5120;
#pragma unroll
        for (int mi = 0; mi < 2; mi++)
#pragma unroll
            for (int ks = 0; ks < 2; ks++) ldsm4(af[mi][ks], aB + mi * 1280 + ks * 32);
#pragma unroll
        for (int ng = 0; ng < 4; ng++)
#pragma unroll
            for (int ks = 0; ks < 2; ks++) ldsm4(bfr[ng][ks], bB + ng * 1280 + ks * 32);
#pragma unroll
        for (int ks = 0; ks < 2; ks++)
#pragma unroll
            for (int mi = 0; mi < 2; mi++)
#pragma unroll
                for (int ni = 0; ni < 8; ni++)
                    mma_f16(acc[mi][ni], af[mi][ks],
                            bfr[ni >> 1][ks][(ni & 1) * 2],
                            bfr[ni >> 1][ks][(ni & 1) * 2 + 1]);
        if (it < nj - 1) { STT_H(b ^ 1); __syncthreads(); }
    }

    int b_ = bh >> 3, h_ = bh & 7;
#pragma unroll
    for (int mi = 0; mi < 2; mi++)
#pragma unroll
        for (int ni = 0; ni < 8; ni++) {
            int t0 = row0 + wy * 32 + mi * 16 + (lane >> 2);
            int d = ni * 8 + (lane & 3) * 2;
#pragma unroll
            for (int half = 0; half < 2; half++) {
                int t = t0 + half * 8;
                __half2 hv = __floats2half2_rn(acc[mi][ni][half * 2],
                                               acc[mi][ni][half * 2 + 1]);
                *(__half2*)(g_Aath + ((size_t)(b_ * 512 + t)) * 512 + h_ * 64 + d) = hv;
            }
        }
}

// ---------------------------------------------------------------------------
extern "C" void kernel_launch(void* const* d_in, const int* in_sizes, int n_in,
                              void* d_out, int out_size)
{
    const float* q  = (const float*)d_in[0];
    const float* k  = (const float*)d_in[1];
    const float* v  = (const float*)d_in[2];
    // d_in[3] = attn_mask — analytic (area end <= t), unused.
    const float* Wq = (const float*)d_in[4];
    const float* bq = (const float*)d_in[5];
    const float* Wk = (const float*)d_in[6];
    const float* bk = (const float*)d_in[7];
    const float* Wv = (const float*)d_in[8];
    const float* bv = (const float*)d_in[9];
    const float* Wo = (const float*)d_in[10];
    const float* bo = (const float*)d_in[11];
    float* out = (float*)d_out;

    cudaFuncSetAttribute(mma_gemm<0>, cudaFuncAttributeMaxDynamicSharedMemorySize, 81920);
    cudaFuncSetAttribute(mma_gemm<1>, cudaFuncAttributeMaxDynamicSharedMemorySize, 81920);
    cudaFuncSetAttribute(gemm_h<0>, cudaFuncAttributeMaxDynamicSharedMemorySize, 81920);
    cudaFuncSetAttribute(gemm_h<1>, cudaFuncAttributeMaxDynamicSharedMemorySize, 81920);
    cudaFuncSetAttribute(qk_mma, cudaFuncAttributeMaxDynamicSharedMemorySize, 81920);

    convW_all<<<dim3(16, 16, 2), 256>>>(Wq, Wk);
    convW_h<<<dim3(16, 16, 2), 256>>>(Wv, Wo);
    convX_all<<<dim3(4096, 1, 2), 256>>>(q, k);
    convV_h<<<4096, 256>>>(v);

    dim3 gG(4, 64);
    mma_gemm<0><<<gG, 128, 81920>>>(bq);
    mma_gemm<1><<<gG, 128, 81920>>>(bk);
    gemm_h<0><<<gG, 128, 81920>>>(bv, nullptr);

    vtrans<<<dim3(8, 128), 256>>>();
    qk_mma<<<dim3(4, 4, 128), 128, 81920>>>();
    area_softmax_kernel<<<dim3(128, 128), 128>>>();
    av_h<<<dim3(4, 128), 128>>>();

    gemm_h<1><<<gG, 128, 81920>>>(bo, out);
}